// round 1
// baseline (speedup 1.0000x reference)
#include <cuda_runtime.h>
#include <math.h>

#define B_     32
#define T0     1600
#define C0     80
#define T1     800
#define D_     512
#define VOCABN 1000
#define HIDN   512
#define USTEPS 200
#define EPSV   1e-3f

// ---------------- scratch (static device globals; no allocation) ----------------
__device__ float g_bn[160];                 // scale[80], shift[80]
__device__ float g_h1[B_ * T1 * D_];        // 52.4 MB
__device__ float g_h2[B_ * T1 * D_];        // 52.4 MB
__device__ float g_hstate[2][B_ * HIDN];    // GRU state ping-pong
__device__ float g_cat[1024 * B_];          // [k][b] transposed concat(h_new, ctx)
__device__ float g_logits[B_ * VOCABN];

// ---------------- BatchNorm statistics (deterministic tree reduce) ----------------
__global__ void __launch_bounds__(256) bn_stats_kernel(const float* __restrict__ x,
                                                       const float* __restrict__ gamma,
                                                       const float* __restrict__ beta) {
    const int c = blockIdx.x;      // 80 channels
    const int tid = threadIdx.x;
    const int N = B_ * T0;         // 51200
    float s = 0.f, sq = 0.f;
    for (int i = tid; i < N; i += 256) {
        float v = x[(size_t)i * C0 + c];
        s += v;
        sq += v * v;
    }
    __shared__ float rs[256], rq[256];
    rs[tid] = s; rq[tid] = sq;
    __syncthreads();
    for (int o = 128; o > 0; o >>= 1) {
        if (tid < o) { rs[tid] += rs[tid + o]; rq[tid] += rq[tid + o]; }
        __syncthreads();
    }
    if (tid == 0) {
        float mean = rs[0] / (float)N;
        float var  = rq[0] / (float)N - mean * mean;
        float sc   = gamma[c] * rsqrtf(var + EPSV);
        g_bn[c]      = sc;
        g_bn[80 + c] = beta[c] - mean * sc;
    }
}

__global__ void __launch_bounds__(512) zero_h_kernel() {
    int i = blockIdx.x * blockDim.x + threadIdx.x;
    if (i < B_ * HIDN) g_hstate[0][i] = 0.f;
}

// ---------------- Conv1D (K=5) as implicit-im2col SGEMM, 64x64x16 tile ----------------
// out[b,t,co] = act( sum_{k,ci} in[b, t*STRIDE - PADL + k, ci] * w[(k*CIN+ci)*512 + co] + bias[co] )
// FUSE_BN: in is normalized on the fly (pad stays exact zero).  RESID: out += in[b,t,co].
template<int CIN, int TIN, int TOUT, int STRIDE, int PADL, bool FUSE_BN, bool RESID>
__global__ void __launch_bounds__(256) conv5_kernel(const float* __restrict__ in,
                                                    const float* __restrict__ w,
                                                    const float* __restrict__ bias,
                                                    float* __restrict__ out) {
    __shared__ __align__(16) float As[16][64];
    __shared__ __align__(16) float Bs[16][64];
    __shared__ __align__(16) float s_bn[160];

    const int tid = threadIdx.x;
    if (FUSE_BN && tid < 160) s_bn[tid] = g_bn[tid];

    const int n0 = blockIdx.x * 64;
    const int m0 = blockIdx.y * 64;
    const int tx = tid & 15;       // col group
    const int ty = tid >> 4;       // row group
    // A-loader mapping: each thread loads float4 of K-dim for one row
    const int arow = tid >> 2;              // 0..63
    const int ak   = (tid & 3) << 2;        // 0,4,8,12
    const int m    = m0 + arow;
    const int bb   = m / TOUT;
    const int t    = m % TOUT;
    // B-loader mapping
    const int bkrow = tid >> 4;             // 0..15
    const int bc    = (tid & 15) << 2;      // 0..60

    float acc[4][4];
#pragma unroll
    for (int i = 0; i < 4; i++)
#pragma unroll
        for (int j = 0; j < 4; j++) acc[i][j] = 0.f;

    __syncthreads();   // s_bn visible before first A-load

    const int KIN = 5 * CIN;
    for (int p0 = 0; p0 < KIN; p0 += 16) {
        // ---- load A tile (im2col) ----
        {
            int p  = p0 + ak;
            int k  = p / CIN;
            int ci = p - k * CIN;           // 4 consecutive ci, same k (CIN % 16 == 0)
            int tin = t * STRIDE - PADL + k;
            float4 av = make_float4(0.f, 0.f, 0.f, 0.f);
            if (tin >= 0 && tin < TIN) {
                av = *reinterpret_cast<const float4*>(in + ((size_t)bb * TIN + tin) * CIN + ci);
                if (FUSE_BN) {
                    float4 sc = *reinterpret_cast<const float4*>(&s_bn[ci]);
                    float4 sh = *reinterpret_cast<const float4*>(&s_bn[80 + ci]);
                    av.x = av.x * sc.x + sh.x;
                    av.y = av.y * sc.y + sh.y;
                    av.z = av.z * sc.z + sh.z;
                    av.w = av.w * sc.w + sh.w;
                }
            }
            As[ak + 0][arow] = av.x;
            As[ak + 1][arow] = av.y;
            As[ak + 2][arow] = av.z;
            As[ak + 3][arow] = av.w;
        }
        // ---- load B tile ----
        *reinterpret_cast<float4*>(&Bs[bkrow][bc]) =
            *reinterpret_cast<const float4*>(w + (size_t)(p0 + bkrow) * 512 + n0 + bc);
        __syncthreads();

#pragma unroll
        for (int kk = 0; kk < 16; kk++) {
            float4 a  = *reinterpret_cast<const float4*>(&As[kk][ty << 2]);
            float4 bv = *reinterpret_cast<const float4*>(&Bs[kk][tx << 2]);
            float aa[4] = {a.x, a.y, a.z, a.w};
            float bw[4] = {bv.x, bv.y, bv.z, bv.w};
#pragma unroll
            for (int i = 0; i < 4; i++)
#pragma unroll
                for (int j = 0; j < 4; j++) acc[i][j] = fmaf(aa[i], bw[j], acc[i][j]);
        }
        __syncthreads();
    }

    // ---- epilogue: bias + relu (+ residual) ----
    const float4 bias4 = *reinterpret_cast<const float4*>(bias + n0 + (tx << 2));
#pragma unroll
    for (int i = 0; i < 4; i++) {
        int mm = m0 + (ty << 2) + i;
        float4 r;
        r.x = fmaxf(acc[i][0] + bias4.x, 0.f);
        r.y = fmaxf(acc[i][1] + bias4.y, 0.f);
        r.z = fmaxf(acc[i][2] + bias4.z, 0.f);
        r.w = fmaxf(acc[i][3] + bias4.w, 0.f);
        if (RESID) {
            float4 res = *reinterpret_cast<const float4*>(in + (size_t)mm * CIN + n0 + (tx << 2));
            r.x += res.x; r.y += res.y; r.z += res.z; r.w += res.w;
        }
        *reinterpret_cast<float4*>(out + (size_t)mm * 512 + n0 + (tx << 2)) = r;
    }
}

// ---------------- Decoder step kernels ----------------
// K0: GRU cell (reset_after). one_hot @ gru_kernel == row gather.
// grid 32 blocks x 512 threads; thread = (b = tid&31, hidden j = blk*16 + tid>>5)
__global__ void __launch_bounds__(512) gru_step_kernel(const int* __restrict__ y,
                                                       const float* __restrict__ gk,
                                                       const float* __restrict__ grk,
                                                       const float* __restrict__ gb,
                                                       int u) {
    __shared__ float sh_h[32][513];
    const int tid = threadIdx.x;
    const float* hp = g_hstate[u & 1];
    for (int i = tid; i < 32 * 512; i += 512) sh_h[i >> 9][i & 511] = hp[i];
    __syncthreads();

    const int b = tid & 31;
    const int j = (blockIdx.x << 4) + (tid >> 5);
    const float* r0 = grk + j;
    float hz = 0.f, hr = 0.f, hh = 0.f;
#pragma unroll 8
    for (int k = 0; k < 512; k++) {
        float hv = sh_h[b][k];
        hz = fmaf(hv, __ldg(r0 + (size_t)k * 1536), hz);
        hr = fmaf(hv, __ldg(r0 + (size_t)k * 1536 + 512), hr);
        hh = fmaf(hv, __ldg(r0 + (size_t)k * 1536 + 1024), hh);
    }
    const int tok = y[b * 201 + u];
    const float* gx = gk + (size_t)tok * 1536;
    float xz = gx[j]        + gb[j];
    float xr = gx[512 + j]  + gb[512 + j];
    float xh = gx[1024 + j] + gb[1024 + j];
    hz += gb[1536 + j];
    hr += gb[1536 + 512 + j];
    hh += gb[1536 + 1024 + j];
    float z = 1.f / (1.f + expf(-(xz + hz)));
    float r = 1.f / (1.f + expf(-(xr + hr)));
    float cand = tanhf(xh + r * hh);
    float hn = z * sh_h[b][j] + (1.f - z) * cand;
    g_hstate[(u + 1) & 1][(b << 9) + j] = hn;
    g_cat[(j << 5) + b] = hn;   // transposed [k][b] for FC coalescing
}

// K1: dot-product attention over enc (block per batch, 512 threads)
__global__ void __launch_bounds__(512) attn_step_kernel(int u) {
    const int b = blockIdx.x;
    const int tid = threadIdx.x;
    __shared__ float sh_h[512];
    __shared__ float sh_s[800];
    __shared__ float red[16], red2[16];

    sh_h[tid] = g_hstate[(u + 1) & 1][(b << 9) + tid];
    __syncthreads();

    const float* encb = g_h1 + (size_t)b * T1 * D_;
    const int warp = tid >> 5, lane = tid & 31;

    // scores: warp per t
    for (int t = warp; t < 800; t += 16) {
        const float* e = encb + (size_t)t * 512;
        float s = 0.f;
#pragma unroll
        for (int k = 0; k < 512; k += 32) s = fmaf(e[k + lane], sh_h[k + lane], s);
#pragma unroll
        for (int o = 16; o; o >>= 1) s += __shfl_xor_sync(0xffffffffu, s, o);
        if (lane == 0) sh_s[t] = s;
    }
    __syncthreads();

    // softmax over 800 (deterministic block reductions)
    float m = -1e30f;
    for (int t = tid; t < 800; t += 512) m = fmaxf(m, sh_s[t]);
#pragma unroll
    for (int o = 16; o; o >>= 1) m = fmaxf(m, __shfl_xor_sync(0xffffffffu, m, o));
    if (lane == 0) red[warp] = m;
    __syncthreads();
    float mm = red[0];
#pragma unroll
    for (int i = 1; i < 16; i++) mm = fmaxf(mm, red[i]);

    float ps = 0.f;
    for (int t = tid; t < 800; t += 512) {
        float e = expf(sh_s[t] - mm);
        sh_s[t] = e;
        ps += e;
    }
#pragma unroll
    for (int o = 16; o; o >>= 1) ps += __shfl_xor_sync(0xffffffffu, ps, o);
    if (lane == 0) red2[warp] = ps;
    __syncthreads();
    float sum = 0.f;
#pragma unroll
    for (int i = 0; i < 16; i++) sum += red2[i];
    const float inv = 1.f / sum;

    // ctx[j]: thread per output dim, coalesced enc reads
    float acc = 0.f;
#pragma unroll 4
    for (int t = 0; t < 800; t++) acc = fmaf(sh_s[t], encb[(size_t)t * 512 + tid], acc);
    g_cat[((512 + tid) << 5) + b] = acc * inv;
}

// K2: logits = cat[1024] @ fc_w[1024,1000] + fc_b   (fc_w read ONCE per step via batch-sharing)
// grid 32 blocks x 256 threads; thread = (b = tid&31, 4 cols at c = blk*32 + (tid>>5)*4)
__global__ void __launch_bounds__(256) fc_step_kernel(const float* __restrict__ fw,
                                                      const float* __restrict__ fb) {
    const int tid = threadIdx.x;
    const int b = tid & 31;
    const int c = (blockIdx.x << 5) + ((tid >> 5) << 2);
    if (c >= 1000) return;
    float a0 = 0.f, a1 = 0.f, a2 = 0.f, a3 = 0.f;
    const float* wp = fw + c;
#pragma unroll 4
    for (int k = 0; k < 1024; k++) {
        float v = g_cat[(k << 5) + b];                  // coalesced: lanes = batches
        float4 wv = *reinterpret_cast<const float4*>(wp + (size_t)k * 1000);  // uniform per warp
        a0 = fmaf(v, wv.x, a0);
        a1 = fmaf(v, wv.y, a1);
        a2 = fmaf(v, wv.z, a2);
        a3 = fmaf(v, wv.w, a3);
    }
    float* lp = g_logits + b * 1000 + c;
    lp[0] = a0 + fb[c];
    lp[1] = a1 + fb[c + 1];
    lp[2] = a2 + fb[c + 2];
    lp[3] = a3 + fb[c + 3];
}

// K3: softmax over 1000 + write output
__global__ void __launch_bounds__(256) outsm_kernel(float* __restrict__ out, int u) {
    const int b = blockIdx.x;
    const int tid = threadIdx.x;
    __shared__ float sh[1000];
    __shared__ float red[8], red2[8];
    const int warp = tid >> 5, lane = tid & 31;

    float m = -1e30f;
    for (int c = tid; c < 1000; c += 256) {
        float v = g_logits[b * 1000 + c];
        sh[c] = v;
        m = fmaxf(m, v);
    }
#pragma unroll
    for (int o = 16; o; o >>= 1) m = fmaxf(m, __shfl_xor_sync(0xffffffffu, m, o));
    if (lane == 0) red[warp] = m;
    __syncthreads();
    float mm = red[0];
#pragma unroll
    for (int i = 1; i < 8; i++) mm = fmaxf(mm, red[i]);

    float ps = 0.f;
    for (int c = tid; c < 1000; c += 256) {
        float e = expf(sh[c] - mm);
        sh[c] = e;
        ps += e;
    }
#pragma unroll
    for (int o = 16; o; o >>= 1) ps += __shfl_xor_sync(0xffffffffu, ps, o);
    if (lane == 0) red2[warp] = ps;
    __syncthreads();
    float sum = 0.f;
#pragma unroll
    for (int i = 0; i < 8; i++) sum += red2[i];
    const float inv = 1.f / sum;

    float* op = out + ((size_t)b * USTEPS + u) * VOCABN;
    for (int c = tid; c < 1000; c += 256) op[c] = sh[c] * inv;
}

// ---------------- launch ----------------
extern "C" void kernel_launch(void* const* d_in, const int* in_sizes, int n_in,
                              void* d_out, int out_size) {
    const float* x        = (const float*)d_in[0];
    const int*   y        = (const int*)  d_in[1];
    const float* bn_gamma = (const float*)d_in[2];
    const float* bn_beta  = (const float*)d_in[3];
    const float* conv0_w  = (const float*)d_in[4];
    const float* conv0_b  = (const float*)d_in[5];
    const float* tcr_w    = (const float*)d_in[6];
    const float* tcr_b    = (const float*)d_in[7];
    const float* gru_k    = (const float*)d_in[8];
    const float* gru_rk   = (const float*)d_in[9];
    const float* gru_b    = (const float*)d_in[10];
    const float* fc_w     = (const float*)d_in[11];
    const float* fc_b     = (const float*)d_in[12];
    float* out = (float*)d_out;

    float *h1, *h2;
    cudaGetSymbolAddress((void**)&h1, g_h1);
    cudaGetSymbolAddress((void**)&h2, g_h2);

    // ---- encoder ----
    bn_stats_kernel<<<80, 256>>>(x, bn_gamma, bn_beta);
    zero_h_kernel<<<32, 512>>>();

    dim3 cgrid(8, 400);   // 512/64 cols, 25600/64 rows
    conv5_kernel<80, 1600, 800, 2, 1, true,  false><<<cgrid, 256>>>(x,  conv0_w, conv0_b, h1);
    const size_t WSZ = (size_t)5 * 512 * 512;
    conv5_kernel<512, 800, 800, 1, 2, false, true><<<cgrid, 256>>>(h1, tcr_w + 0 * WSZ, tcr_b + 0 * 512, h2);
    conv5_kernel<512, 800, 800, 1, 2, false, true><<<cgrid, 256>>>(h2, tcr_w + 1 * WSZ, tcr_b + 1 * 512, h1);
    conv5_kernel<512, 800, 800, 1, 2, false, true><<<cgrid, 256>>>(h1, tcr_w + 2 * WSZ, tcr_b + 2 * 512, h2);
    conv5_kernel<512, 800, 800, 1, 2, false, true><<<cgrid, 256>>>(h2, tcr_w + 3 * WSZ, tcr_b + 3 * 512, h1);
    // enc lives in g_h1

    // ---- decoder: 200 teacher-forced steps ----
    for (int u = 0; u < USTEPS; u++) {
        gru_step_kernel<<<32, 512>>>(y, gru_k, gru_rk, gru_b, u);
        attn_step_kernel<<<32, 512>>>(u);
        fc_step_kernel<<<32, 256>>>(fc_w, fc_b);
        outsm_kernel<<<32, 256>>>(out, u);
    }
}

// round 3
// speedup vs baseline: 2.8879x; 2.8879x over previous
#include <cuda_runtime.h>
#include <math.h>

typedef unsigned long long ull;

#define B_     32
#define T0     1600
#define C0     80
#define T1     800
#define D_     512
#define VOCABN 1000
#define HIDN   512
#define USTEPS 200
#define EPSV   1e-3f

// ---------------- scratch (static device globals; no allocation) ----------------
__device__ float g_bn[160];                     // scale[80], shift[80]
__device__ float g_h1[B_ * T1 * D_];            // 52.4 MB
__device__ float g_h2[B_ * T1 * D_];            // 52.4 MB
__device__ float g_hstate[2][B_ * HIDN];        // GRU state ping-pong
__device__ float g_mh[B_ * 1536];               // h @ gru_rec_kernel
__device__ float g_scores[B_ * T1];             // attention scores (one step)
__device__ float g_catall[USTEPS * B_ * 1024];  // 26.2 MB: [u*32+b][1024] = concat(h_new, ctx)
__device__ float g_logitsall[USTEPS * B_ * VOCABN]; // 25.6 MB

// ---------------- packed f32x2 helpers (FFMA2) ----------------
__device__ __forceinline__ void fma2(ull& d, ull a, ull b) {
    asm("fma.rn.f32x2 %0, %1, %2, %0;" : "+l"(d) : "l"(a), "l"(b));
}
__device__ __forceinline__ ull pack2(float x) {
    ull r;
    asm("mov.b64 %0, {%1, %1};" : "=l"(r) : "f"(x));
    return r;
}
__device__ __forceinline__ float2 unpack2(ull v) {
    float2 f;
    asm("mov.b64 {%0, %1}, %2;" : "=f"(f.x), "=f"(f.y) : "l"(v));
    return f;
}

// ---------------- BatchNorm statistics ----------------
__global__ void __launch_bounds__(256) bn_stats_kernel(const float* __restrict__ x,
                                                       const float* __restrict__ gamma,
                                                       const float* __restrict__ beta) {
    const int c = blockIdx.x;
    const int tid = threadIdx.x;
    const int N = B_ * T0;
    float s = 0.f, sq = 0.f;
    for (int i = tid; i < N; i += 256) {
        float v = x[(size_t)i * C0 + c];
        s += v; sq += v * v;
    }
    __shared__ float rs[256], rq[256];
    rs[tid] = s; rq[tid] = sq;
    __syncthreads();
    for (int o = 128; o > 0; o >>= 1) {
        if (tid < o) { rs[tid] += rs[tid + o]; rq[tid] += rq[tid + o]; }
        __syncthreads();
    }
    if (tid == 0) {
        float mean = rs[0] / (float)N;
        float var  = rq[0] / (float)N - mean * mean;
        float sc   = gamma[c] * rsqrtf(var + EPSV);
        g_bn[c]      = sc;
        g_bn[80 + c] = beta[c] - mean * sc;
    }
}

__global__ void __launch_bounds__(512) zero_h_kernel() {
    int i = blockIdx.x * blockDim.x + threadIdx.x;
    if (i < B_ * HIDN) g_hstate[0][i] = 0.f;
}

// ---------------- Conv1D (K=5) implicit-im2col SGEMM, 128x128x16 tile, FFMA2 ----------------
template<int CIN, int TIN, int TOUT, int STRIDE, int PADL, bool FUSE_BN, bool RESID>
__global__ void __launch_bounds__(256, 2) conv5x_kernel(const float* __restrict__ in,
                                                        const float* __restrict__ w,
                                                        const float* __restrict__ bias,
                                                        float* __restrict__ out) {
    __shared__ __align__(16) float As[16][128];
    __shared__ __align__(16) float Bs[16][128];
    __shared__ __align__(16) float s_bn[160];

    const int tid = threadIdx.x;
    if (FUSE_BN && tid < 160) s_bn[tid] = g_bn[tid];

    const int n0 = blockIdx.x * 128;
    const int m0 = blockIdx.y * 128;
    const int tx = tid & 15;       // n group (8 cols at tx*8)
    const int ty = tid >> 4;       // m group (8 rows at ty*8)

    ull acc[8][4];
#pragma unroll
    for (int i = 0; i < 8; i++)
#pragma unroll
        for (int j = 0; j < 4; j++) acc[i][j] = 0ull;

    __syncthreads();   // s_bn visible

    const int KIN = 5 * CIN;
    for (int p0 = 0; p0 < KIN; p0 += 16) {
        // ---- load A tile (im2col): 512 float4 slots, 2 per thread ----
#pragma unroll
        for (int it = 0; it < 2; it++) {
            int s  = tid + it * 256;
            int kq = s & 3;                 // k quad (4 floats of K)
            int ml = s >> 2;                // 0..127
            int p  = p0 + (kq << 2);
            int k  = p / CIN;
            int ci = p - k * CIN;
            int m  = m0 + ml;
            int bb = m / TOUT;
            int t  = m - bb * TOUT;
            int tin = t * STRIDE - PADL + k;
            float4 av = make_float4(0.f, 0.f, 0.f, 0.f);
            if (tin >= 0 && tin < TIN) {
                av = *reinterpret_cast<const float4*>(in + ((size_t)bb * TIN + tin) * CIN + ci);
                if (FUSE_BN) {
                    float4 sc = *reinterpret_cast<const float4*>(&s_bn[ci]);
                    float4 sh = *reinterpret_cast<const float4*>(&s_bn[80 + ci]);
                    av.x = av.x * sc.x + sh.x;
                    av.y = av.y * sc.y + sh.y;
                    av.z = av.z * sc.z + sh.z;
                    av.w = av.w * sc.w + sh.w;
                }
            }
            As[(kq << 2) + 0][ml] = av.x;
            As[(kq << 2) + 1][ml] = av.y;
            As[(kq << 2) + 2][ml] = av.z;
            As[(kq << 2) + 3][ml] = av.w;
        }
        // ---- load B tile: 512 float4 slots, 2 per thread ----
#pragma unroll
        for (int it = 0; it < 2; it++) {
            int s  = tid + it * 256;
            int cq = s & 31;
            int kr = s >> 5;
            *reinterpret_cast<float4*>(&Bs[kr][cq << 2]) =
                *reinterpret_cast<const float4*>(w + (size_t)(p0 + kr) * 512 + n0 + (cq << 2));
        }
        __syncthreads();

#pragma unroll
        for (int kk = 0; kk < 16; kk++) {
            float4 a0 = *reinterpret_cast<const float4*>(&As[kk][ty << 3]);
            float4 a1 = *reinterpret_cast<const float4*>(&As[kk][(ty << 3) + 4]);
            ull b0 = *reinterpret_cast<const ull*>(&Bs[kk][(tx << 3) + 0]);
            ull b1 = *reinterpret_cast<const ull*>(&Bs[kk][(tx << 3) + 2]);
            ull b2 = *reinterpret_cast<const ull*>(&Bs[kk][(tx << 3) + 4]);
            ull b3 = *reinterpret_cast<const ull*>(&Bs[kk][(tx << 3) + 6]);
            float av[8] = {a0.x, a0.y, a0.z, a0.w, a1.x, a1.y, a1.z, a1.w};
#pragma unroll
            for (int i = 0; i < 8; i++) {
                ull a2 = pack2(av[i]);
                fma2(acc[i][0], a2, b0);
                fma2(acc[i][1], a2, b1);
                fma2(acc[i][2], a2, b2);
                fma2(acc[i][3], a2, b3);
            }
        }
        __syncthreads();
    }

    // ---- epilogue: bias + relu (+ residual) ----
    const float4 bias0 = *reinterpret_cast<const float4*>(bias + n0 + (tx << 3));
    const float4 bias1 = *reinterpret_cast<const float4*>(bias + n0 + (tx << 3) + 4);
#pragma unroll
    for (int i = 0; i < 8; i++) {
        int m = m0 + (ty << 3) + i;
        float2 p0v = unpack2(acc[i][0]);
        float2 p1v = unpack2(acc[i][1]);
        float2 p2v = unpack2(acc[i][2]);
        float2 p3v = unpack2(acc[i][3]);
        float4 r0, r1;
        r0.x = fmaxf(p0v.x + bias0.x, 0.f);
        r0.y = fmaxf(p0v.y + bias0.y, 0.f);
        r0.z = fmaxf(p1v.x + bias0.z, 0.f);
        r0.w = fmaxf(p1v.y + bias0.w, 0.f);
        r1.x = fmaxf(p2v.x + bias1.x, 0.f);
        r1.y = fmaxf(p2v.y + bias1.y, 0.f);
        r1.z = fmaxf(p3v.x + bias1.z, 0.f);
        r1.w = fmaxf(p3v.y + bias1.w, 0.f);
        if (RESID) {
            float4 e0 = *reinterpret_cast<const float4*>(in + (size_t)m * CIN + n0 + (tx << 3));
            float4 e1 = *reinterpret_cast<const float4*>(in + (size_t)m * CIN + n0 + (tx << 3) + 4);
            r0.x += e0.x; r0.y += e0.y; r0.z += e0.z; r0.w += e0.w;
            r1.x += e1.x; r1.y += e1.y; r1.z += e1.z; r1.w += e1.w;
        }
        *reinterpret_cast<float4*>(out + (size_t)m * 512 + n0 + (tx << 3))     = r0;
        *reinterpret_cast<float4*>(out + (size_t)m * 512 + n0 + (tx << 3) + 4) = r1;
    }
}

// ---------------- Decoder ----------------
// D0: mh = h @ gru_rec_kernel  (C[32,1536] = H[32,512] x W[512,1536]); grid 12, block 256
__global__ void __launch_bounds__(256) gru_gemm_kernel(const float* __restrict__ grk, int u) {
    __shared__ float Hst[16][33];
    __shared__ __align__(16) float Ws[16][128];
    const float* h = g_hstate[u & 1];
    const int tid = threadIdx.x;
    const int n0 = blockIdx.x * 128;
    const int nx = tid & 31;   // n = n0 + nx*4
    const int my = tid >> 5;   // m = my*4 .. +4
    float acc[4][4];
#pragma unroll
    for (int i = 0; i < 4; i++)
#pragma unroll
        for (int j = 0; j < 4; j++) acc[i][j] = 0.f;

    for (int k0 = 0; k0 < 512; k0 += 16) {
#pragma unroll
        for (int it = 0; it < 2; it++) {
            int e = tid + it * 256;
            int kk = e & 15, m = e >> 4;
            Hst[kk][m] = h[m * 512 + k0 + kk];
        }
#pragma unroll
        for (int it = 0; it < 2; it++) {
            int s = tid + it * 256;
            int cq = s & 31, kr = s >> 5;
            *reinterpret_cast<float4*>(&Ws[kr][cq << 2]) =
                *reinterpret_cast<const float4*>(grk + (size_t)(k0 + kr) * 1536 + n0 + (cq << 2));
        }
        __syncthreads();
#pragma unroll
        for (int kk = 0; kk < 16; kk++) {
            float a0 = Hst[kk][(my << 2) + 0];
            float a1 = Hst[kk][(my << 2) + 1];
            float a2 = Hst[kk][(my << 2) + 2];
            float a3 = Hst[kk][(my << 2) + 3];
            float4 bv = *reinterpret_cast<const float4*>(&Ws[kk][nx << 2]);
            acc[0][0] = fmaf(a0, bv.x, acc[0][0]); acc[0][1] = fmaf(a0, bv.y, acc[0][1]);
            acc[0][2] = fmaf(a0, bv.z, acc[0][2]); acc[0][3] = fmaf(a0, bv.w, acc[0][3]);
            acc[1][0] = fmaf(a1, bv.x, acc[1][0]); acc[1][1] = fmaf(a1, bv.y, acc[1][1]);
            acc[1][2] = fmaf(a1, bv.z, acc[1][2]); acc[1][3] = fmaf(a1, bv.w, acc[1][3]);
            acc[2][0] = fmaf(a2, bv.x, acc[2][0]); acc[2][1] = fmaf(a2, bv.y, acc[2][1]);
            acc[2][2] = fmaf(a2, bv.z, acc[2][2]); acc[2][3] = fmaf(a2, bv.w, acc[2][3]);
            acc[3][0] = fmaf(a3, bv.x, acc[3][0]); acc[3][1] = fmaf(a3, bv.y, acc[3][1]);
            acc[3][2] = fmaf(a3, bv.z, acc[3][2]); acc[3][3] = fmaf(a3, bv.w, acc[3][3]);
        }
        __syncthreads();
    }
#pragma unroll
    for (int i = 0; i < 4; i++) {
        float4 r = make_float4(acc[i][0], acc[i][1], acc[i][2], acc[i][3]);
        *reinterpret_cast<float4*>(&g_mh[((my << 2) + i) * 1536 + n0 + (nx << 2)]) = r;
    }
}

// D1: GRU gates (redundant per t-chunk) + attention scores.
// grid (8 t-chunks, 32 b) x 256 threads
__global__ void __launch_bounds__(256) attn_scores_kernel(const int* __restrict__ y,
                                                          const float* __restrict__ gk,
                                                          const float* __restrict__ gb,
                                                          int u) {
    __shared__ __align__(16) float sh_h[512];
    const int b = blockIdx.y, tc = blockIdx.x, tid = threadIdx.x;
    const float* mh   = g_mh + b * 1536;
    const float* bi   = gb;
    const float* br   = gb + 1536;
    const int tok     = y[b * 201 + u];
    const float* gx   = gk + (size_t)tok * 1536;
    const float* hold = g_hstate[u & 1] + b * 512;
    float* hnew       = g_hstate[(u + 1) & 1] + b * 512;
    float* catrow     = g_catall + ((size_t)u * 32 + b) * 1024;

#pragma unroll
    for (int it = 0; it < 2; it++) {
        int j = tid + it * 256;
        float xz = gx[j]        + bi[j];
        float xr = gx[512 + j]  + bi[512 + j];
        float xh = gx[1024 + j] + bi[1024 + j];
        float hz = mh[j]        + br[j];
        float hr = mh[512 + j]  + br[512 + j];
        float hh = mh[1024 + j] + br[1024 + j];
        float z = 1.f / (1.f + expf(-(xz + hz)));
        float r = 1.f / (1.f + expf(-(xr + hr)));
        float cand = tanhf(xh + r * hh);
        float hn = z * hold[j] + (1.f - z) * cand;
        sh_h[j] = hn;
        if (tc == 0) { hnew[j] = hn; catrow[j] = hn; }
    }
    __syncthreads();

    const int w = tid >> 5, lane = tid & 31;
    const float4* h4 = reinterpret_cast<const float4*>(sh_h);
    const int tbase = tc * 100;
    for (int t = tbase + w; t < tbase + 100; t += 8) {
        const float4* e4 = reinterpret_cast<const float4*>(g_h1 + ((size_t)b * T1 + t) * 512);
        float s = 0.f;
#pragma unroll
        for (int i = 0; i < 4; i++) {
            float4 ev = e4[lane + 32 * i];
            float4 hv = h4[lane + 32 * i];
            s += ev.x * hv.x + ev.y * hv.y + ev.z * hv.z + ev.w * hv.w;
        }
#pragma unroll
        for (int o = 16; o; o >>= 1) s += __shfl_xor_sync(0xffffffffu, s, o);
        if (lane == 0) g_scores[b * T1 + t] = s;
    }
}

// D2: softmax (redundant per d-chunk) + ctx. grid (8 d-chunks, 32 b) x 256
__global__ void __launch_bounds__(256) attn_ctx_kernel(int u) {
    __shared__ float sa[800];
    __shared__ float red[8], red2[8];
    __shared__ float part[4][64];
    const int b = blockIdx.y, dc = blockIdx.x, tid = threadIdx.x;
    const int w = tid >> 5, lane = tid & 31;

    float m = -1e30f;
    for (int t = tid; t < 800; t += 256) {
        float v = g_scores[b * T1 + t];
        sa[t] = v;
        m = fmaxf(m, v);
    }
#pragma unroll
    for (int o = 16; o; o >>= 1) m = fmaxf(m, __shfl_xor_sync(0xffffffffu, m, o));
    if (lane == 0) red[w] = m;
    __syncthreads();
    float mm = red[0];
#pragma unroll
    for (int i = 1; i < 8; i++) mm = fmaxf(mm, red[i]);

    float ps = 0.f;
    for (int t = tid; t < 800; t += 256) {
        float e = expf(sa[t] - mm);
        sa[t] = e;
        ps += e;
    }
#pragma unroll
    for (int o = 16; o; o >>= 1) ps += __shfl_xor_sync(0xffffffffu, ps, o);
    if (lane == 0) red2[w] = ps;
    __syncthreads();
    float sum = 0.f;
#pragma unroll
    for (int i = 0; i < 8; i++) sum += red2[i];
    const float inv = 1.f / sum;

    const int tg = tid >> 6;     // 0..3
    const int d  = tid & 63;
    const int d0 = dc * 64;
    const float* encd = g_h1 + (size_t)b * T1 * 512 + d0 + d;
    float acc = 0.f;
#pragma unroll 4
    for (int t = tg; t < 800; t += 4) acc = fmaf(sa[t], encd[(size_t)t * 512], acc);
    part[tg][d] = acc;
    __syncthreads();
    if (tid < 64) {
        float v = part[0][tid] + part[1][tid] + part[2][tid] + part[3][tid];
        g_catall[((size_t)u * 32 + b) * 1024 + 512 + d0 + tid] = v * inv;
    }
}

// ---------------- Batched FC: logits[6400,1000] = cat[6400,1024] @ fc_w + fc_b ----------------
__global__ void __launch_bounds__(256, 2) fc_big_kernel(const float* __restrict__ fw,
                                                        const float* __restrict__ fb) {
    __shared__ __align__(16) float As[16][128];
    __shared__ __align__(16) float Bs[16][128];
    const int tid = threadIdx.x;
    const int n0 = blockIdx.x * 128;
    const int m0 = blockIdx.y * 128;
    const int tx = tid & 15;
    const int ty = tid >> 4;

    ull acc[8][4];
#pragma unroll
    for (int i = 0; i < 8; i++)
#pragma unroll
        for (int j = 0; j < 4; j++) acc[i][j] = 0ull;

    for (int p0 = 0; p0 < 1024; p0 += 16) {
#pragma unroll
        for (int it = 0; it < 2; it++) {
            int s  = tid + it * 256;
            int kq = s & 3;
            int ml = s >> 2;
            float4 av = *reinterpret_cast<const float4*>(
                g_catall + ((size_t)(m0 + ml)) * 1024 + p0 + (kq << 2));
            As[(kq << 2) + 0][ml] = av.x;
            As[(kq << 2) + 1][ml] = av.y;
            As[(kq << 2) + 2][ml] = av.z;
            As[(kq << 2) + 3][ml] = av.w;
        }
#pragma unroll
        for (int it = 0; it < 2; it++) {
            int s  = tid + it * 256;
            int cq = s & 31;
            int kr = s >> 5;
            int c  = n0 + (cq << 2);
            float4 v = make_float4(0.f, 0.f, 0.f, 0.f);
            if (c < 1000)
                v = *reinterpret_cast<const float4*>(fw + (size_t)(p0 + kr) * 1000 + c);
            *reinterpret_cast<float4*>(&Bs[kr][cq << 2]) = v;
        }
        __syncthreads();

#pragma unroll
        for (int kk = 0; kk < 16; kk++) {
            float4 a0 = *reinterpret_cast<const float4*>(&As[kk][ty << 3]);
            float4 a1 = *reinterpret_cast<const float4*>(&As[kk][(ty << 3) + 4]);
            ull b0 = *reinterpret_cast<const ull*>(&Bs[kk][(tx << 3) + 0]);
            ull b1 = *reinterpret_cast<const ull*>(&Bs[kk][(tx << 3) + 2]);
            ull b2 = *reinterpret_cast<const ull*>(&Bs[kk][(tx << 3) + 4]);
            ull b3 = *reinterpret_cast<const ull*>(&Bs[kk][(tx << 3) + 6]);
            float av[8] = {a0.x, a0.y, a0.z, a0.w, a1.x, a1.y, a1.z, a1.w};
#pragma unroll
            for (int i = 0; i < 8; i++) {
                ull a2 = pack2(av[i]);
                fma2(acc[i][0], a2, b0);
                fma2(acc[i][1], a2, b1);
                fma2(acc[i][2], a2, b2);
                fma2(acc[i][3], a2, b3);
            }
        }
        __syncthreads();
    }

    const int c0 = n0 + (tx << 3);
    float bias[8];
#pragma unroll
    for (int j = 0; j < 8; j++) bias[j] = (c0 + j < 1000) ? fb[c0 + j] : 0.f;
#pragma unroll
    for (int i = 0; i < 8; i++) {
        int m = m0 + (ty << 3) + i;
        float2 p0v = unpack2(acc[i][0]);
        float2 p1v = unpack2(acc[i][1]);
        float2 p2v = unpack2(acc[i][2]);
        float2 p3v = unpack2(acc[i][3]);
        float4 r0 = make_float4(p0v.x + bias[0], p0v.y + bias[1], p1v.x + bias[2], p1v.y + bias[3]);
        float4 r1 = make_float4(p2v.x + bias[4], p2v.y + bias[5], p3v.x + bias[6], p3v.y + bias[7]);
        float* lp = g_logitsall + (size_t)m * 1000;
        if (c0 < 1000)     *reinterpret_cast<float4*>(lp + c0)     = r0;
        if (c0 + 4 < 1000) *reinterpret_cast<float4*>(lp + c0 + 4) = r1;
    }
}

// ---------------- Batched output softmax: 6400 rows ----------------
__global__ void __launch_bounds__(256) outsm_all_kernel(float* __restrict__ out) {
    const int m = blockIdx.x;            // m = u*32 + b
    const int u = m >> 5, b = m & 31;
    const int tid = threadIdx.x;
    __shared__ float sh[1000];
    __shared__ float red[8], red2[8];
    const int w = tid >> 5, lane = tid & 31;
    const float* lp = g_logitsall + (size_t)m * 1000;

    float mx = -1e30f;
    for (int c = tid; c < 1000; c += 256) {
        float v = lp[c];
        sh[c] = v;
        mx = fmaxf(mx, v);
    }
#pragma unroll
    for (int o = 16; o; o >>= 1) mx = fmaxf(mx, __shfl_xor_sync(0xffffffffu, mx, o));
    if (lane == 0) red[w] = mx;
    __syncthreads();
    float mm = red[0];
#pragma unroll
    for (int i = 1; i < 8; i++) mm = fmaxf(mm, red[i]);

    float ps = 0.f;
    for (int c = tid; c < 1000; c += 256) {
        float e = expf(sh[c] - mm);
        sh[c] = e;
        ps += e;
    }
#pragma unroll
    for (int o = 16; o; o >>= 1) ps += __shfl_xor_sync(0xffffffffu, ps, o);
    if (lane == 0) red2[w] = ps;
    __syncthreads();
    float sum = 0.f;
#pragma unroll
    for (int i = 0; i < 8; i++) sum += red2[i];
    const float inv = 1.f / sum;

    float* op = out + ((size_t)b * USTEPS + u) * VOCABN;
    for (int c = tid; c < 1000; c += 256) op[c] = sh[c] * inv;
}

// ---------------- launch ----------------
extern "C" void kernel_launch(void* const* d_in, const int* in_sizes, int n_in,
                              void* d_out, int out_size) {
    const float* x        = (const float*)d_in[0];
    const int*   y        = (const int*)  d_in[1];
    const float* bn_gamma = (const float*)d_in[2];
    const float* bn_beta  = (const float*)d_in[3];
    const float* conv0_w  = (const float*)d_in[4];
    const float* conv0_b  = (const float*)d_in[5];
    const float* tcr_w    = (const float*)d_in[6];
    const float* tcr_b    = (const float*)d_in[7];
    const float* gru_k    = (const float*)d_in[8];
    const float* gru_rk   = (const float*)d_in[9];
    const float* gru_b    = (const float*)d_in[10];
    const float* fc_w     = (const float*)d_in[11];
    const float* fc_b     = (const float*)d_in[12];
    float* out = (float*)d_out;

    float *h1, *h2;
    cudaGetSymbolAddress((void**)&h1, g_h1);
    cudaGetSymbolAddress((void**)&h2, g_h2);

    // ---- encoder ----
    bn_stats_kernel<<<80, 256>>>(x, bn_gamma, bn_beta);
    zero_h_kernel<<<32, 512>>>();

    dim3 cgrid(4, 200);   // 512/128 cols, 25600/128 rows
    conv5x_kernel<80, 1600, 800, 2, 1, true,  false><<<cgrid, 256>>>(x,  conv0_w, conv0_b, h1);
    const size_t WSZ = (size_t)5 * 512 * 512;
    conv5x_kernel<512, 800, 800, 1, 2, false, true><<<cgrid, 256>>>(h1, tcr_w + 0 * WSZ, tcr_b + 0 * 512, h2);
    conv5x_kernel<512, 800, 800, 1, 2, false, true><<<cgrid, 256>>>(h2, tcr_w + 1 * WSZ, tcr_b + 1 * 512, h1);
    conv5x_kernel<512, 800, 800, 1, 2, false, true><<<cgrid, 256>>>(h1, tcr_w + 2 * WSZ, tcr_b + 2 * 512, h2);
    conv5x_kernel<512, 800, 800, 1, 2, false, true><<<cgrid, 256>>>(h2, tcr_w + 3 * WSZ, tcr_b + 3 * 512, h1);
    // enc lives in g_h1

    // ---- decoder recurrence: 3 kernels per step (FC/softmax batched after) ----
    dim3 sgrid(8, 32);
    for (int u = 0; u < USTEPS; u++) {
        gru_gemm_kernel<<<12, 256>>>(gru_rk, u);
        attn_scores_kernel<<<sgrid, 256>>>(y, gru_k, gru_b, u);
        attn_ctx_kernel<<<sgrid, 256>>>(u);
    }

    // ---- batched projection + softmax over all 200 steps ----
    dim3 fgrid(8, 50);    // 1024/128 col tiles (guarded to 1000), 6400/128 row tiles
    fc_big_kernel<<<fgrid, 256>>>(fc_w, fc_b);
    outsm_all_kernel<<<USTEPS * B_, 256>>>(out);
}

// round 4
// speedup vs baseline: 3.7085x; 1.2841x over previous
#include <cuda_runtime.h>
#include <math.h>

typedef unsigned long long ull;

#define B_     32
#define T0     1600
#define C0     80
#define T1     800
#define D_     512
#define VOCABN 1000
#define HIDN   512
#define USTEPS 200
#define EPSV   1e-3f

// ---------------- scratch (static device globals; no allocation) ----------------
__device__ float g_bn[160];                         // scale[80], shift[80]
__device__ float g_h1[B_ * T1 * D_];                // 52.4 MB (enc)
__device__ float g_h2[B_ * T1 * D_];                // 52.4 MB
__device__ float g_hstate[2][B_ * HIDN];            // GRU state ping-pong
__device__ float g_mh[B_ * 1536];                   // h @ gru_rec_kernel
__device__ float g_scoresall[USTEPS * B_ * T1];     // 20.5 MB: [u*32+b][800]
__device__ float g_catall[USTEPS * B_ * 1024];      // 26.2 MB: [u*32+b][1024]
__device__ float g_logitsall[USTEPS * B_ * VOCABN]; // 25.6 MB

// ---------------- packed f32x2 helpers (FFMA2) ----------------
__device__ __forceinline__ void fma2(ull& d, ull a, ull b) {
    asm("fma.rn.f32x2 %0, %1, %2, %0;" : "+l"(d) : "l"(a), "l"(b));
}
__device__ __forceinline__ ull pack2(float x) {
    ull r;
    asm("mov.b64 %0, {%1, %1};" : "=l"(r) : "f"(x));
    return r;
}
__device__ __forceinline__ ull pack2f(float x, float y) {
    ull r;
    asm("mov.b64 %0, {%1, %2};" : "=l"(r) : "f"(x), "f"(y));
    return r;
}
__device__ __forceinline__ float2 unpack2(ull v) {
    float2 f;
    asm("mov.b64 {%0, %1}, %2;" : "=f"(f.x), "=f"(f.y) : "l"(v));
    return f;
}

// ---------------- BatchNorm statistics ----------------
__global__ void __launch_bounds__(256) bn_stats_kernel(const float* __restrict__ x,
                                                       const float* __restrict__ gamma,
                                                       const float* __restrict__ beta) {
    const int c = blockIdx.x;
    const int tid = threadIdx.x;
    const int N = B_ * T0;
    float s = 0.f, sq = 0.f;
    for (int i = tid; i < N; i += 256) {
        float v = x[(size_t)i * C0 + c];
        s += v; sq += v * v;
    }
    __shared__ float rs[256], rq[256];
    rs[tid] = s; rq[tid] = sq;
    __syncthreads();
    for (int o = 128; o > 0; o >>= 1) {
        if (tid < o) { rs[tid] += rs[tid + o]; rq[tid] += rq[tid + o]; }
        __syncthreads();
    }
    if (tid == 0) {
        float mean = rs[0] / (float)N;
        float var  = rq[0] / (float)N - mean * mean;
        float sc   = gamma[c] * rsqrtf(var + EPSV);
        g_bn[c]      = sc;
        g_bn[80 + c] = beta[c] - mean * sc;
    }
}

__global__ void __launch_bounds__(512) zero_h_kernel() {
    int i = blockIdx.x * blockDim.x + threadIdx.x;
    if (i < B_ * HIDN) g_hstate[0][i] = 0.f;
}

// ---------------- Conv1D (K=5) implicit-im2col SGEMM, 128x128x32 tile, FFMA2 ----------------
// A-tile smem stores XOR-swizzled: phys_col = col ^ ((row>>2)<<2)  (conflict-free stores)
// B-tile read as 2x float4 at columns tx*4 and 64+tx*4 (covers all 32 banks)
template<int CIN, int TIN, int TOUT, int STRIDE, int PADL, bool FUSE_BN, bool RESID>
__global__ void __launch_bounds__(256, 2) conv5x_kernel(const float* __restrict__ in,
                                                        const float* __restrict__ w,
                                                        const float* __restrict__ bias,
                                                        float* __restrict__ out) {
    __shared__ __align__(16) float As[32][128];
    __shared__ __align__(16) float Bs[32][128];
    __shared__ __align__(16) float s_bn[160];

    const int tid = threadIdx.x;
    if (FUSE_BN && tid < 160) s_bn[tid] = g_bn[tid];

    const int n0 = blockIdx.x * 128;
    const int m0 = blockIdx.y * 128;
    const int tx = tid & 15;       // columns: n0+tx*4 (..+3) and n0+64+tx*4 (..+3)
    const int ty = tid >> 4;       // rows: m0+ty*8 .. +7

    ull acc[8][4];
#pragma unroll
    for (int i = 0; i < 8; i++)
#pragma unroll
        for (int j = 0; j < 4; j++) acc[i][j] = 0ull;

    __syncthreads();   // s_bn visible

    const int KIN = 5 * CIN;
    for (int p0 = 0; p0 < KIN; p0 += 32) {
        // ---- load A tile (im2col): 1024 float4 slots, 4 per thread ----
#pragma unroll
        for (int it = 0; it < 4; it++) {
            int s  = tid + it * 256;
            int kq = s & 7;                 // k quad within 32-k tile
            int ml = s >> 3;                // 0..127
            int p  = p0 + (kq << 2);
            int k  = p / CIN;
            int ci = p - k * CIN;
            int m  = m0 + ml;
            int bb = m / TOUT;
            int t  = m - bb * TOUT;
            int tin = t * STRIDE - PADL + k;
            float4 av = make_float4(0.f, 0.f, 0.f, 0.f);
            if (tin >= 0 && tin < TIN && p < KIN) {
                av = *reinterpret_cast<const float4*>(in + ((size_t)bb * TIN + tin) * CIN + ci);
                if (FUSE_BN) {
                    float4 sc = *reinterpret_cast<const float4*>(&s_bn[ci]);
                    float4 sh = *reinterpret_cast<const float4*>(&s_bn[80 + ci]);
                    av.x = av.x * sc.x + sh.x;
                    av.y = av.y * sc.y + sh.y;
                    av.z = av.z * sc.z + sh.z;
                    av.w = av.w * sc.w + sh.w;
                }
            }
            int pc = ml ^ (kq << 2);        // row group = kq -> swizzle
            As[(kq << 2) + 0][pc] = av.x;
            As[(kq << 2) + 1][pc] = av.y;
            As[(kq << 2) + 2][pc] = av.z;
            As[(kq << 2) + 3][pc] = av.w;
        }
        // ---- load B tile: 1024 float4 slots, 4 per thread ----
#pragma unroll
        for (int it = 0; it < 4; it++) {
            int s  = tid + it * 256;
            int cq = s & 31;
            int kr = s >> 5;
            float4 v = make_float4(0.f, 0.f, 0.f, 0.f);
            if (p0 + kr < KIN)
                v = *reinterpret_cast<const float4*>(w + (size_t)(p0 + kr) * 512 + n0 + (cq << 2));
            *reinterpret_cast<float4*>(&Bs[kr][cq << 2]) = v;
        }
        __syncthreads();

#pragma unroll
        for (int kk = 0; kk < 32; kk++) {
            const int sw = (kk >> 2) << 2;
            float4 a0 = *reinterpret_cast<const float4*>(&As[kk][(ty << 3) ^ sw]);
            float4 a1 = *reinterpret_cast<const float4*>(&As[kk][((ty << 3) + 4) ^ sw]);
            float4 bA = *reinterpret_cast<const float4*>(&Bs[kk][tx << 2]);
            float4 bB = *reinterpret_cast<const float4*>(&Bs[kk][64 + (tx << 2)]);
            ull b0 = pack2f(bA.x, bA.y);
            ull b1 = pack2f(bA.z, bA.w);
            ull b2 = pack2f(bB.x, bB.y);
            ull b3 = pack2f(bB.z, bB.w);
            float av[8] = {a0.x, a0.y, a0.z, a0.w, a1.x, a1.y, a1.z, a1.w};
#pragma unroll
            for (int i = 0; i < 8; i++) {
                ull a2 = pack2(av[i]);
                fma2(acc[i][0], a2, b0);
                fma2(acc[i][1], a2, b1);
                fma2(acc[i][2], a2, b2);
                fma2(acc[i][3], a2, b3);
            }
        }
        __syncthreads();
    }

    // ---- epilogue: bias + relu (+ residual); columns c0 and c1 ----
    const int c0 = n0 + (tx << 2);
    const int c1 = n0 + 64 + (tx << 2);
    const float4 bias0 = *reinterpret_cast<const float4*>(bias + c0);
    const float4 bias1 = *reinterpret_cast<const float4*>(bias + c1);
#pragma unroll
    for (int i = 0; i < 8; i++) {
        int m = m0 + (ty << 3) + i;
        float2 p0v = unpack2(acc[i][0]);
        float2 p1v = unpack2(acc[i][1]);
        float2 p2v = unpack2(acc[i][2]);
        float2 p3v = unpack2(acc[i][3]);
        float4 r0, r1;
        r0.x = fmaxf(p0v.x + bias0.x, 0.f);
        r0.y = fmaxf(p0v.y + bias0.y, 0.f);
        r0.z = fmaxf(p1v.x + bias0.z, 0.f);
        r0.w = fmaxf(p1v.y + bias0.w, 0.f);
        r1.x = fmaxf(p2v.x + bias1.x, 0.f);
        r1.y = fmaxf(p2v.y + bias1.y, 0.f);
        r1.z = fmaxf(p3v.x + bias1.z, 0.f);
        r1.w = fmaxf(p3v.y + bias1.w, 0.f);
        if (RESID) {
            float4 e0 = *reinterpret_cast<const float4*>(in + (size_t)m * CIN + c0);
            float4 e1 = *reinterpret_cast<const float4*>(in + (size_t)m * CIN + c1);
            r0.x += e0.x; r0.y += e0.y; r0.z += e0.z; r0.w += e0.w;
            r1.x += e1.x; r1.y += e1.y; r1.z += e1.z; r1.w += e1.w;
        }
        *reinterpret_cast<float4*>(out + (size_t)m * 512 + c0) = r0;
        *reinterpret_cast<float4*>(out + (size_t)m * 512 + c1) = r1;
    }
}

// ---------------- Decoder recurrence ----------------
// D0: mh = h @ gru_rec_kernel  (C[32,1536] = H[32,512] x W[512,1536]); grid 12, block 256
__global__ void __launch_bounds__(256) gru_gemm_kernel(const float* __restrict__ grk, int u) {
    __shared__ float Hst[16][33];
    __shared__ __align__(16) float Ws[16][128];
    const float* h = g_hstate[u & 1];
    const int tid = threadIdx.x;
    const int n0 = blockIdx.x * 128;
    const int nx = tid & 31;   // n = n0 + nx*4
    const int my = tid >> 5;   // m = my*4 .. +4
    float acc[4][4];
#pragma unroll
    for (int i = 0; i < 4; i++)
#pragma unroll
        for (int j = 0; j < 4; j++) acc[i][j] = 0.f;

    for (int k0 = 0; k0 < 512; k0 += 16) {
#pragma unroll
        for (int it = 0; it < 2; it++) {
            int e = tid + it * 256;
            int kk = e & 15, m = e >> 4;
            Hst[kk][m] = h[m * 512 + k0 + kk];
        }
#pragma unroll
        for (int it = 0; it < 2; it++) {
            int s = tid + it * 256;
            int cq = s & 31, kr = s >> 5;
            *reinterpret_cast<float4*>(&Ws[kr][cq << 2]) =
                *reinterpret_cast<const float4*>(grk + (size_t)(k0 + kr) * 1536 + n0 + (cq << 2));
        }
        __syncthreads();
#pragma unroll
        for (int kk = 0; kk < 16; kk++) {
            float a0 = Hst[kk][(my << 2) + 0];
            float a1 = Hst[kk][(my << 2) + 1];
            float a2 = Hst[kk][(my << 2) + 2];
            float a3 = Hst[kk][(my << 2) + 3];
            float4 bv = *reinterpret_cast<const float4*>(&Ws[kk][nx << 2]);
            acc[0][0] = fmaf(a0, bv.x, acc[0][0]); acc[0][1] = fmaf(a0, bv.y, acc[0][1]);
            acc[0][2] = fmaf(a0, bv.z, acc[0][2]); acc[0][3] = fmaf(a0, bv.w, acc[0][3]);
            acc[1][0] = fmaf(a1, bv.x, acc[1][0]); acc[1][1] = fmaf(a1, bv.y, acc[1][1]);
            acc[1][2] = fmaf(a1, bv.z, acc[1][2]); acc[1][3] = fmaf(a1, bv.w, acc[1][3]);
            acc[2][0] = fmaf(a2, bv.x, acc[2][0]); acc[2][1] = fmaf(a2, bv.y, acc[2][1]);
            acc[2][2] = fmaf(a2, bv.z, acc[2][2]); acc[2][3] = fmaf(a2, bv.w, acc[2][3]);
            acc[3][0] = fmaf(a3, bv.x, acc[3][0]); acc[3][1] = fmaf(a3, bv.y, acc[3][1]);
            acc[3][2] = fmaf(a3, bv.z, acc[3][2]); acc[3][3] = fmaf(a3, bv.w, acc[3][3]);
        }
        __syncthreads();
    }
#pragma unroll
    for (int i = 0; i < 4; i++) {
        float4 r = make_float4(acc[i][0], acc[i][1], acc[i][2], acc[i][3]);
        *reinterpret_cast<float4*>(&g_mh[((my << 2) + i) * 1536 + n0 + (nx << 2)]) = r;
    }
}

// D1: GRU gates (redundant per t-chunk) + attention scores -> g_scoresall.
// grid (8 t-chunks, 32 b) x 256 threads
__global__ void __launch_bounds__(256) attn_scores_kernel(const int* __restrict__ y,
                                                          const float* __restrict__ gk,
                                                          const float* __restrict__ gb,
                                                          int u) {
    __shared__ __align__(16) float sh_h[512];
    const int b = blockIdx.y, tc = blockIdx.x, tid = threadIdx.x;
    const float* mh   = g_mh + b * 1536;
    const float* bi   = gb;
    const float* br   = gb + 1536;
    const int tok     = y[b * 201 + u];
    const float* gx   = gk + (size_t)tok * 1536;
    const float* hold = g_hstate[u & 1] + b * 512;
    float* hnew       = g_hstate[(u + 1) & 1] + b * 512;
    float* catrow     = g_catall + ((size_t)u * 32 + b) * 1024;
    float* scorerow   = g_scoresall + ((size_t)u * 32 + b) * T1;

#pragma unroll
    for (int it = 0; it < 2; it++) {
        int j = tid + it * 256;
        float xz = gx[j]        + bi[j];
        float xr = gx[512 + j]  + bi[512 + j];
        float xh = gx[1024 + j] + bi[1024 + j];
        float hz = mh[j]        + br[j];
        float hr = mh[512 + j]  + br[512 + j];
        float hh = mh[1024 + j] + br[1024 + j];
        float z = 1.f / (1.f + expf(-(xz + hz)));
        float r = 1.f / (1.f + expf(-(xr + hr)));
        float cand = tanhf(xh + r * hh);
        float hn = z * hold[j] + (1.f - z) * cand;
        sh_h[j] = hn;
        if (tc == 0) { hnew[j] = hn; catrow[j] = hn; }
    }
    __syncthreads();

    const int w = tid >> 5, lane = tid & 31;
    const float4* h4 = reinterpret_cast<const float4*>(sh_h);
    const int tbase = tc * 100;
    for (int t = tbase + w; t < tbase + 100; t += 8) {
        const float4* e4 = reinterpret_cast<const float4*>(g_h1 + ((size_t)b * T1 + t) * 512);
        float s = 0.f;
#pragma unroll
        for (int i = 0; i < 4; i++) {
            float4 ev = e4[lane + 32 * i];
            float4 hv = h4[lane + 32 * i];
            s += ev.x * hv.x + ev.y * hv.y + ev.z * hv.z + ev.w * hv.w;
        }
#pragma unroll
        for (int o = 16; o; o >>= 1) s += __shfl_xor_sync(0xffffffffu, s, o);
        if (lane == 0) scorerow[t] = s;
    }
}

// ---------------- Batched softmax over 800 (all 6400 rows), in place ----------------
__global__ void __launch_bounds__(256) sm800_kernel() {
    const int row = blockIdx.x;
    const int tid = threadIdx.x;
    float* sp = g_scoresall + (size_t)row * T1;
    __shared__ float sa[800];
    __shared__ float red[8], red2[8];
    const int w = tid >> 5, lane = tid & 31;

    float m = -1e30f;
    for (int t = tid; t < 800; t += 256) {
        float v = sp[t];
        sa[t] = v;
        m = fmaxf(m, v);
    }
#pragma unroll
    for (int o = 16; o; o >>= 1) m = fmaxf(m, __shfl_xor_sync(0xffffffffu, m, o));
    if (lane == 0) red[w] = m;
    __syncthreads();
    float mm = red[0];
#pragma unroll
    for (int i = 1; i < 8; i++) mm = fmaxf(mm, red[i]);

    float ps = 0.f;
    for (int t = tid; t < 800; t += 256) {
        float e = expf(sa[t] - mm);
        sa[t] = e;
        ps += e;
    }
#pragma unroll
    for (int o = 16; o; o >>= 1) ps += __shfl_xor_sync(0xffffffffu, ps, o);
    if (lane == 0) red2[w] = ps;
    __syncthreads();
    float sum = 0.f;
#pragma unroll
    for (int i = 0; i < 8; i++) sum += red2[i];
    const float inv = 1.f / sum;

    for (int t = tid; t < 800; t += 256) sp[t] = sa[t] * inv;
}

// ---------------- Batched ctx: per b, alpha[200,800] @ enc_b[800,512] ----------------
// grid (4 n-tiles, 2 m-tiles, 32 b), block 256; 128x128x16 tiles, FFMA2
__global__ void __launch_bounds__(256, 2) ctx_gemm_kernel() {
    __shared__ __align__(16) float As[16][128];
    __shared__ __align__(16) float Bs[16][128];
    const int tid = threadIdx.x;
    const int n0 = blockIdx.x * 128;
    const int m0 = blockIdx.y * 128;   // row = step u
    const int b  = blockIdx.z;
    const int tx = tid & 15;
    const int ty = tid >> 4;

    ull acc[8][4];
#pragma unroll
    for (int i = 0; i < 8; i++)
#pragma unroll
        for (int j = 0; j < 4; j++) acc[i][j] = 0ull;

    for (int k0 = 0; k0 < 800; k0 += 16) {
#pragma unroll
        for (int it = 0; it < 2; it++) {
            int s  = tid + it * 256;
            int kq = s & 3;
            int ml = s >> 2;
            int u  = m0 + ml;
            float4 av = make_float4(0.f, 0.f, 0.f, 0.f);
            if (u < USTEPS)
                av = *reinterpret_cast<const float4*>(
                    g_scoresall + ((size_t)u * 32 + b) * T1 + k0 + (kq << 2));
            As[(kq << 2) + 0][ml] = av.x;
            As[(kq << 2) + 1][ml] = av.y;
            As[(kq << 2) + 2][ml] = av.z;
            As[(kq << 2) + 3][ml] = av.w;
        }
#pragma unroll
        for (int it = 0; it < 2; it++) {
            int s  = tid + it * 256;
            int cq = s & 31;
            int kr = s >> 5;
            *reinterpret_cast<float4*>(&Bs[kr][cq << 2]) =
                *reinterpret_cast<const float4*>(
                    g_h1 + ((size_t)b * T1 + k0 + kr) * 512 + n0 + (cq << 2));
        }
        __syncthreads();

#pragma unroll
        for (int kk = 0; kk < 16; kk++) {
            float4 a0 = *reinterpret_cast<const float4*>(&As[kk][ty << 3]);
            float4 a1 = *reinterpret_cast<const float4*>(&As[kk][(ty << 3) + 4]);
            ull b0 = *reinterpret_cast<const ull*>(&Bs[kk][(tx << 3) + 0]);
            ull b1 = *reinterpret_cast<const ull*>(&Bs[kk][(tx << 3) + 2]);
            ull b2 = *reinterpret_cast<const ull*>(&Bs[kk][(tx << 3) + 4]);
            ull b3 = *reinterpret_cast<const ull*>(&Bs[kk][(tx << 3) + 6]);
            float av[8] = {a0.x, a0.y, a0.z, a0.w, a1.x, a1.y, a1.z, a1.w};
#pragma unroll
            for (int i = 0; i < 8; i++) {
                ull a2 = pack2(av[i]);
                fma2(acc[i][0], a2, b0);
                fma2(acc[i][1], a2, b1);
                fma2(acc[i][2], a2, b2);
                fma2(acc[i][3], a2, b3);
            }
        }
        __syncthreads();
    }

#pragma unroll
    for (int i = 0; i < 8; i++) {
        int u = m0 + (ty << 3) + i;
        if (u < USTEPS) {
            float2 p0v = unpack2(acc[i][0]);
            float2 p1v = unpack2(acc[i][1]);
            float2 p2v = unpack2(acc[i][2]);
            float2 p3v = unpack2(acc[i][3]);
            float4 r0 = make_float4(p0v.x, p0v.y, p1v.x, p1v.y);
            float4 r1 = make_float4(p2v.x, p2v.y, p3v.x, p3v.y);
            float* cp = g_catall + ((size_t)u * 32 + b) * 1024 + 512 + n0 + (tx << 3);
            *reinterpret_cast<float4*>(cp)     = r0;
            *reinterpret_cast<float4*>(cp + 4) = r1;
        }
    }
}

// ---------------- Batched FC: logits[6400,1000] = cat[6400,1024] @ fc_w + fc_b ----------------
__global__ void __launch_bounds__(256, 2) fc_big_kernel(const float* __restrict__ fw,
                                                        const float* __restrict__ fb) {
    __shared__ __align__(16) float As[16][128];
    __shared__ __align__(16) float Bs[16][128];
    const int tid = threadIdx.x;
    const int n0 = blockIdx.x * 128;
    const int m0 = blockIdx.y * 128;
    const int tx = tid & 15;
    const int ty = tid >> 4;

    ull acc[8][4];
#pragma unroll
    for (int i = 0; i < 8; i++)
#pragma unroll
        for (int j = 0; j < 4; j++) acc[i][j] = 0ull;

    for (int p0 = 0; p0 < 1024; p0 += 16) {
#pragma unroll
        for (int it = 0; it < 2; it++) {
            int s  = tid + it * 256;
            int kq = s & 3;
            int ml = s >> 2;
            float4 av = *reinterpret_cast<const float4*>(
                g_catall + ((size_t)(m0 + ml)) * 1024 + p0 + (kq << 2));
            As[(kq << 2) + 0][ml] = av.x;
            As[(kq << 2) + 1][ml] = av.y;
            As[(kq << 2) + 2][ml] = av.z;
            As[(kq << 2) + 3][ml] = av.w;
        }
#pragma unroll
        for (int it = 0; it < 2; it++) {
            int s  = tid + it * 256;
            int cq = s & 31;
            int kr = s >> 5;
            int c  = n0 + (cq << 2);
            float4 v = make_float4(0.f, 0.f, 0.f, 0.f);
            if (c < 1000)
                v = *reinterpret_cast<const float4*>(fw + (size_t)(p0 + kr) * 1000 + c);
            *reinterpret_cast<float4*>(&Bs[kr][cq << 2]) = v;
        }
        __syncthreads();

#pragma unroll
        for (int kk = 0; kk < 16; kk++) {
            float4 a0 = *reinterpret_cast<const float4*>(&As[kk][ty << 3]);
            float4 a1 = *reinterpret_cast<const float4*>(&As[kk][(ty << 3) + 4]);
            ull b0 = *reinterpret_cast<const ull*>(&Bs[kk][(tx << 3) + 0]);
            ull b1 = *reinterpret_cast<const ull*>(&Bs[kk][(tx << 3) + 2]);
            ull b2 = *reinterpret_cast<const ull*>(&Bs[kk][(tx << 3) + 4]);
            ull b3 = *reinterpret_cast<const ull*>(&Bs[kk][(tx << 3) + 6]);
            float av[8] = {a0.x, a0.y, a0.z, a0.w, a1.x, a1.y, a1.z, a1.w};
#pragma unroll
            for (int i = 0; i < 8; i++) {
                ull a2 = pack2(av[i]);
                fma2(acc[i][0], a2, b0);
                fma2(acc[i][1], a2, b1);
                fma2(acc[i][2], a2, b2);
                fma2(acc[i][3], a2, b3);
            }
        }
        __syncthreads();
    }

    const int c0 = n0 + (tx << 3);
    float bias[8];
#pragma unroll
    for (int j = 0; j < 8; j++) bias[j] = (c0 + j < 1000) ? fb[c0 + j] : 0.f;
#pragma unroll
    for (int i = 0; i < 8; i++) {
        int m = m0 + (ty << 3) + i;
        float2 p0v = unpack2(acc[i][0]);
        float2 p1v = unpack2(acc[i][1]);
        float2 p2v = unpack2(acc[i][2]);
        float2 p3v = unpack2(acc[i][3]);
        float4 r0 = make_float4(p0v.x + bias[0], p0v.y + bias[1], p1v.x + bias[2], p1v.y + bias[3]);
        float4 r1 = make_float4(p2v.x + bias[4], p2v.y + bias[5], p3v.x + bias[6], p3v.y + bias[7]);
        float* lp = g_logitsall + (size_t)m * 1000;
        if (c0 < 1000)     *reinterpret_cast<float4*>(lp + c0)     = r0;
        if (c0 + 4 < 1000) *reinterpret_cast<float4*>(lp + c0 + 4) = r1;
    }
}

// ---------------- Batched output softmax: 6400 rows ----------------
__global__ void __launch_bounds__(256) outsm_all_kernel(float* __restrict__ out) {
    const int m = blockIdx.x;            // m = u*32 + b
    const int u = m >> 5, b = m & 31;
    const int tid = threadIdx.x;
    __shared__ float sh[1000];
    __shared__ float red[8], red2[8];
    const int w = tid >> 5, lane = tid & 31;
    const float* lp = g_logitsall + (size_t)m * 1000;

    float mx = -1e30f;
    for (int c = tid; c < 1000; c += 256) {
        float v = lp[c];
        sh[c] = v;
        mx = fmaxf(mx, v);
    }
#pragma unroll
    for (int o = 16; o; o >>= 1) mx = fmaxf(mx, __shfl_xor_sync(0xffffffffu, mx, o));
    if (lane == 0) red[w] = mx;
    __syncthreads();
    float mm = red[0];
#pragma unroll
    for (int i = 1; i < 8; i++) mm = fmaxf(mm, red[i]);

    float ps = 0.f;
    for (int c = tid; c < 1000; c += 256) {
        float e = expf(sh[c] - mm);
        sh[c] = e;
        ps += e;
    }
#pragma unroll
    for (int o = 16; o; o >>= 1) ps += __shfl_xor_sync(0xffffffffu, ps, o);
    if (lane == 0) red2[w] = ps;
    __syncthreads();
    float sum = 0.f;
#pragma unroll
    for (int i = 0; i < 8; i++) sum += red2[i];
    const float inv = 1.f / sum;

    float* op = out + ((size_t)b * USTEPS + u) * VOCABN;
    for (int c = tid; c < 1000; c += 256) op[c] = sh[c] * inv;
}

// ---------------- launch ----------------
extern "C" void kernel_launch(void* const* d_in, const int* in_sizes, int n_in,
                              void* d_out, int out_size) {
    const float* x        = (const float*)d_in[0];
    const int*   y        = (const int*)  d_in[1];
    const float* bn_gamma = (const float*)d_in[2];
    const float* bn_beta  = (const float*)d_in[3];
    const float* conv0_w  = (const float*)d_in[4];
    const float* conv0_b  = (const float*)d_in[5];
    const float* tcr_w    = (const float*)d_in[6];
    const float* tcr_b    = (const float*)d_in[7];
    const float* gru_k    = (const float*)d_in[8];
    const float* gru_rk   = (const float*)d_in[9];
    const float* gru_b    = (const float*)d_in[10];
    const float* fc_w     = (const float*)d_in[11];
    const float* fc_b     = (const float*)d_in[12];
    float* out = (float*)d_out;

    float *h1, *h2;
    cudaGetSymbolAddress((void**)&h1, g_h1);
    cudaGetSymbolAddress((void**)&h2, g_h2);

    // ---- encoder ----
    bn_stats_kernel<<<80, 256>>>(x, bn_gamma, bn_beta);
    zero_h_kernel<<<32, 512>>>();

    dim3 cgrid(4, 200);   // 512/128 cols, 25600/128 rows
    conv5x_kernel<80, 1600, 800, 2, 1, true,  false><<<cgrid, 256>>>(x,  conv0_w, conv0_b, h1);
    const size_t WSZ = (size_t)5 * 512 * 512;
    conv5x_kernel<512, 800, 800, 1, 2, false, true><<<cgrid, 256>>>(h1, tcr_w + 0 * WSZ, tcr_b + 0 * 512, h2);
    conv5x_kernel<512, 800, 800, 1, 2, false, true><<<cgrid, 256>>>(h2, tcr_w + 1 * WSZ, tcr_b + 1 * 512, h1);
    conv5x_kernel<512, 800, 800, 1, 2, false, true><<<cgrid, 256>>>(h1, tcr_w + 2 * WSZ, tcr_b + 2 * 512, h2);
    conv5x_kernel<512, 800, 800, 1, 2, false, true><<<cgrid, 256>>>(h2, tcr_w + 3 * WSZ, tcr_b + 3 * 512, h1);
    // enc lives in g_h1

    // ---- decoder recurrence: 2 kernels per step ----
    dim3 sgrid(8, 32);
    for (int u = 0; u < USTEPS; u++) {
        gru_gemm_kernel<<<12, 256>>>(gru_rk, u);
        attn_scores_kernel<<<sgrid, 256>>>(y, gru_k, gru_b, u);
    }

    // ---- batched tail: softmax(scores), ctx GEMM, FC, output softmax ----
    sm800_kernel<<<USTEPS * B_, 256>>>();
    dim3 xgrid(4, 2, 32);
    ctx_gemm_kernel<<<xgrid, 256>>>();
    dim3 fgrid(8, 50);
    fc_big_kernel<<<fgrid, 256>>>(fc_w, fc_b);
    outsm_all_kernel<<<USTEPS * B_, 256>>>(out);
}

// round 5
// speedup vs baseline: 5.8241x; 1.5705x over previous
#include <cuda_runtime.h>
#include <math.h>

typedef unsigned long long ull;

#define B_     32
#define T0     1600
#define C0     80
#define T1     800
#define D_     512
#define VOCABN 1000
#define HIDN   512
#define USTEPS 200
#define EPSV   1e-3f

// ---------------- scratch (static device globals; no allocation) ----------------
__device__ float g_bn[160];
__device__ float g_h1[B_ * T1 * D_];                // enc
__device__ float g_h2[B_ * T1 * D_];
__device__ float g_hstate[2][B_ * HIDN];
__device__ float g_mhp[4][B_ * 1536];               // k-split partials of h @ grk
__device__ float g_scoresall[USTEPS * B_ * T1];     // [u*32+b][800]
__device__ float g_catall[USTEPS * B_ * 1024];      // [u*32+b][1024] = concat(h_new, ctx)
__device__ float g_logitsall[USTEPS * B_ * VOCABN];

// ---------------- packed f32x2 helpers (FFMA2) ----------------
__device__ __forceinline__ void fma2(ull& d, ull a, ull b) {
    asm("fma.rn.f32x2 %0, %1, %2, %0;" : "+l"(d) : "l"(a), "l"(b));
}
__device__ __forceinline__ ull pack2(float x) {
    ull r;
    asm("mov.b64 %0, {%1, %1};" : "=l"(r) : "f"(x));
    return r;
}
__device__ __forceinline__ float2 unpack2(ull v) {
    float2 f;
    asm("mov.b64 {%0, %1}, %2;" : "=f"(f.x), "=f"(f.y) : "l"(v));
    return f;
}

// ---------------- BatchNorm statistics ----------------
__global__ void __launch_bounds__(256) bn_stats_kernel(const float* __restrict__ x,
                                                       const float* __restrict__ gamma,
                                                       const float* __restrict__ beta) {
    const int c = blockIdx.x;
    const int tid = threadIdx.x;
    const int N = B_ * T0;
    float s = 0.f, sq = 0.f;
    for (int i = tid; i < N; i += 256) {
        float v = x[(size_t)i * C0 + c];
        s += v; sq += v * v;
    }
    __shared__ float rs[256], rq[256];
    rs[tid] = s; rq[tid] = sq;
    __syncthreads();
    for (int o = 128; o > 0; o >>= 1) {
        if (tid < o) { rs[tid] += rs[tid + o]; rq[tid] += rq[tid + o]; }
        __syncthreads();
    }
    if (tid == 0) {
        float mean = rs[0] / (float)N;
        float var  = rq[0] / (float)N - mean * mean;
        float sc   = gamma[c] * rsqrtf(var + EPSV);
        g_bn[c]      = sc;
        g_bn[80 + c] = beta[c] - mean * sc;
    }
}

__global__ void __launch_bounds__(512) zero_h_kernel() {
    int i = blockIdx.x * blockDim.x + threadIdx.x;
    if (i < B_ * HIDN) g_hstate[0][i] = 0.f;
}

// ---------------- Conv1D (K=5) implicit-im2col SGEMM, 128x128x32, FFMA2 m-paired ----------------
template<int CIN, int TIN, int TOUT, int STRIDE, int PADL, bool FUSE_BN, bool RESID>
__global__ void __launch_bounds__(256, 2) conv5x_kernel(const float* __restrict__ in,
                                                        const float* __restrict__ w,
                                                        const float* __restrict__ bias,
                                                        float* __restrict__ out) {
    __shared__ __align__(16) float As[32][128];
    __shared__ __align__(16) float Bs[32][128];
    __shared__ __align__(16) float s_bn[160];

    const int tid = threadIdx.x;
    if (FUSE_BN && tid < 160) s_bn[tid] = g_bn[tid];

    const int n0 = blockIdx.x * 128;
    const int m0 = blockIdx.y * 128;
    const int tx = tid & 15;       // cols: n0+tx*4 (..+3) and n0+64+tx*4 (..+3)
    const int ty = tid >> 4;       // rows: m0+ty*8 .. +7 (as 4 m-pairs)

    // acc[mp][n]: mp = m-pair 0..3 (rows ty*8+2mp, +1); n 0..3 -> c0 group, 4..7 -> c1 group
    ull acc[4][8];
#pragma unroll
    for (int i = 0; i < 4; i++)
#pragma unroll
        for (int j = 0; j < 8; j++) acc[i][j] = 0ull;

    __syncthreads();

    const int KIN = 5 * CIN;
    for (int p0 = 0; p0 < KIN; p0 += 32) {
        // ---- A tile (im2col), stored [k][m] with XOR swizzle ----
#pragma unroll
        for (int it = 0; it < 4; it++) {
            int s  = tid + it * 256;
            int kq = s & 7;
            int ml = s >> 3;
            int p  = p0 + (kq << 2);
            int k  = p / CIN;
            int ci = p - k * CIN;
            int m  = m0 + ml;
            int bb = m / TOUT;
            int t  = m - bb * TOUT;
            int tin = t * STRIDE - PADL + k;
            float4 av = make_float4(0.f, 0.f, 0.f, 0.f);
            if (tin >= 0 && tin < TIN && p < KIN) {
                av = *reinterpret_cast<const float4*>(in + ((size_t)bb * TIN + tin) * CIN + ci);
                if (FUSE_BN) {
                    float4 sc = *reinterpret_cast<const float4*>(&s_bn[ci]);
                    float4 sh = *reinterpret_cast<const float4*>(&s_bn[80 + ci]);
                    av.x = av.x * sc.x + sh.x;
                    av.y = av.y * sc.y + sh.y;
                    av.z = av.z * sc.z + sh.z;
                    av.w = av.w * sc.w + sh.w;
                }
            }
            int pc = ml ^ (kq << 2);
            As[(kq << 2) + 0][pc] = av.x;
            As[(kq << 2) + 1][pc] = av.y;
            As[(kq << 2) + 2][pc] = av.z;
            As[(kq << 2) + 3][pc] = av.w;
        }
        // ---- B tile (row-major, no transpose) ----
#pragma unroll
        for (int it = 0; it < 4; it++) {
            int s  = tid + it * 256;
            int cq = s & 31;
            int kr = s >> 5;
            float4 v = make_float4(0.f, 0.f, 0.f, 0.f);
            if (p0 + kr < KIN)
                v = *reinterpret_cast<const float4*>(w + (size_t)(p0 + kr) * 512 + n0 + (cq << 2));
            *reinterpret_cast<float4*>(&Bs[kr][cq << 2]) = v;
        }
        __syncthreads();

#pragma unroll
        for (int kk = 0; kk < 32; kk++) {
            const int sw = (kk >> 2) << 2;
            // A: two float4 = 4 m-pairs, directly usable (no movs)
            ulonglong2 ap0 = *reinterpret_cast<const ulonglong2*>(&As[kk][(ty << 3) ^ sw]);
            ulonglong2 ap1 = *reinterpret_cast<const ulonglong2*>(&As[kk][((ty << 3) + 4) ^ sw]);
            ull ap[4] = {ap0.x, ap0.y, ap1.x, ap1.y};
            float4 bA = *reinterpret_cast<const float4*>(&Bs[kk][tx << 2]);
            float4 bB = *reinterpret_cast<const float4*>(&Bs[kk][64 + (tx << 2)]);
            ull bd[8];
            bd[0] = pack2(bA.x); bd[1] = pack2(bA.y); bd[2] = pack2(bA.z); bd[3] = pack2(bA.w);
            bd[4] = pack2(bB.x); bd[5] = pack2(bB.y); bd[6] = pack2(bB.z); bd[7] = pack2(bB.w);
#pragma unroll
            for (int mp = 0; mp < 4; mp++)
#pragma unroll
                for (int n = 0; n < 8; n++) fma2(acc[mp][n], ap[mp], bd[n]);
        }
        __syncthreads();
    }

    // ---- epilogue ----
    const int c0 = n0 + (tx << 2);
    const int c1 = n0 + 64 + (tx << 2);
    const float4 bias0 = *reinterpret_cast<const float4*>(bias + c0);
    const float4 bias1 = *reinterpret_cast<const float4*>(bias + c1);
    float2 u0[4][4], u1[4][4];
#pragma unroll
    for (int mp = 0; mp < 4; mp++)
#pragma unroll
        for (int n = 0; n < 4; n++) {
            u0[mp][n] = unpack2(acc[mp][n]);
            u1[mp][n] = unpack2(acc[mp][4 + n]);
        }
#pragma unroll
    for (int i = 0; i < 8; i++) {
        const int mp = i >> 1;
        const bool hi = i & 1;
        int m = m0 + (ty << 3) + i;
        float4 r0, r1;
        r0.x = fmaxf((hi ? u0[mp][0].y : u0[mp][0].x) + bias0.x, 0.f);
        r0.y = fmaxf((hi ? u0[mp][1].y : u0[mp][1].x) + bias0.y, 0.f);
        r0.z = fmaxf((hi ? u0[mp][2].y : u0[mp][2].x) + bias0.z, 0.f);
        r0.w = fmaxf((hi ? u0[mp][3].y : u0[mp][3].x) + bias0.w, 0.f);
        r1.x = fmaxf((hi ? u1[mp][0].y : u1[mp][0].x) + bias1.x, 0.f);
        r1.y = fmaxf((hi ? u1[mp][1].y : u1[mp][1].x) + bias1.y, 0.f);
        r1.z = fmaxf((hi ? u1[mp][2].y : u1[mp][2].x) + bias1.z, 0.f);
        r1.w = fmaxf((hi ? u1[mp][3].y : u1[mp][3].x) + bias1.w, 0.f);
        if (RESID) {
            float4 e0 = *reinterpret_cast<const float4*>(in + (size_t)m * CIN + c0);
            float4 e1 = *reinterpret_cast<const float4*>(in + (size_t)m * CIN + c1);
            r0.x += e0.x; r0.y += e0.y; r0.z += e0.z; r0.w += e0.w;
            r1.x += e1.x; r1.y += e1.y; r1.z += e1.z; r1.w += e1.w;
        }
        *reinterpret_cast<float4*>(out + (size_t)m * 512 + c0) = r0;
        *reinterpret_cast<float4*>(out + (size_t)m * 512 + c1) = r1;
    }
}

// ---------------- Recurrence kernel A: mh partials (k-split GEMM) ----------------
// grid (12 n-tiles, 4 k-chunks), block 256.  g_mhp[kc][b][n] = sum_{k in chunk} h[b][k] grk[k][n]
__global__ void __launch_bounds__(256) gru_part_kernel(const float* __restrict__ grk, int u) {
    __shared__ float Hs[16][33];
    __shared__ __align__(16) float Ws[16][128];
    const float* h = g_hstate[u & 1];
    const int tid = threadIdx.x;
    const int n0 = blockIdx.x * 128;
    const int kb = blockIdx.y * 128;
    const int nx = tid & 31;   // n = n0 + nx*4
    const int my = tid >> 5;   // b = my*4 .. +3

    ull acc[4][2];
#pragma unroll
    for (int i = 0; i < 4; i++) { acc[i][0] = 0ull; acc[i][1] = 0ull; }

    for (int k0 = 0; k0 < 128; k0 += 16) {
#pragma unroll
        for (int it = 0; it < 2; it++) {
            int e = tid + it * 256;
            int kk = e & 15, m = e >> 4;
            Hs[kk][m] = h[m * 512 + kb + k0 + kk];
        }
#pragma unroll
        for (int it = 0; it < 2; it++) {
            int s = tid + it * 256;
            int cq = s & 31, kr = s >> 5;
            *reinterpret_cast<float4*>(&Ws[kr][cq << 2]) =
                *reinterpret_cast<const float4*>(grk + (size_t)(kb + k0 + kr) * 1536 + n0 + (cq << 2));
        }
        __syncthreads();
#pragma unroll
        for (int kk = 0; kk < 16; kk++) {
            ulonglong2 bp = *reinterpret_cast<const ulonglong2*>(&Ws[kk][nx << 2]);
#pragma unroll
            for (int i = 0; i < 4; i++) {
                ull ad = pack2(Hs[kk][(my << 2) + i]);
                fma2(acc[i][0], ad, bp.x);
                fma2(acc[i][1], ad, bp.y);
            }
        }
        __syncthreads();
    }
    float* outp = g_mhp[blockIdx.y];
#pragma unroll
    for (int i = 0; i < 4; i++) {
        float2 v0 = unpack2(acc[i][0]);
        float2 v1 = unpack2(acc[i][1]);
        *reinterpret_cast<float4*>(&outp[((my << 2) + i) * 1536 + n0 + (nx << 2)]) =
            make_float4(v0.x, v0.y, v1.x, v1.y);
    }
}

// ---------------- Recurrence kernel B: sum partials + GRU gates ----------------
// grid 32 (b), 512 threads (j)
__global__ void __launch_bounds__(512) gru_gates_kernel(const int* __restrict__ y,
                                                        const float* __restrict__ gk,
                                                        const float* __restrict__ gb,
                                                        int u) {
    const int b = blockIdx.x;
    const int j = threadIdx.x;
    float hz = 0.f, hr = 0.f, hh = 0.f;
#pragma unroll
    for (int c = 0; c < 4; c++) {
        const float* p = g_mhp[c] + b * 1536;
        hz += p[j];
        hr += p[512 + j];
        hh += p[1024 + j];
    }
    const float* bi = gb;
    const float* br = gb + 1536;
    const int tok   = y[b * 201 + u];
    const float* gx = gk + (size_t)tok * 1536;
    float xz = gx[j]        + bi[j];
    float xr = gx[512 + j]  + bi[512 + j];
    float xh = gx[1024 + j] + bi[1024 + j];
    hz += br[j];
    hr += br[512 + j];
    hh += br[1024 + j];
    float z = 1.f / (1.f + expf(-(xz + hz)));
    float r = 1.f / (1.f + expf(-(xr + hr)));
    float cand = tanhf(xh + r * hh);
    float hold = g_hstate[u & 1][b * 512 + j];
    float hn = z * hold + (1.f - z) * cand;
    g_hstate[(u + 1) & 1][b * 512 + j] = hn;
    g_catall[((size_t)u * 32 + b) * 1024 + j] = hn;
}

// ---------------- Batched scores GEMM: per b, S[200,800] = H[200,512] @ enc_b^T ----------------
// grid (7 n-tiles of t, 2 m-tiles of u, 32 b), block 256; A and B both transposed+swizzled into smem.
__global__ void __launch_bounds__(256, 2) scores_gemm_kernel() {
    __shared__ __align__(16) float As[16][128];
    __shared__ __align__(16) float Bs[16][128];
    const int tid = threadIdx.x;
    const int n0 = blockIdx.x * 128;   // t
    const int m0 = blockIdx.y * 128;   // u
    const int b  = blockIdx.z;
    const int tx = tid & 15;
    const int ty = tid >> 4;

    ull acc[8][4];
#pragma unroll
    for (int i = 0; i < 8; i++)
#pragma unroll
        for (int j = 0; j < 4; j++) acc[i][j] = 0ull;

    for (int k0 = 0; k0 < 512; k0 += 16) {
        // A: rows u (stride 32*1024), k contiguous
#pragma unroll
        for (int it = 0; it < 2; it++) {
            int s  = tid + it * 256;
            int kq = s & 3;
            int ml = s >> 2;
            int urow = m0 + ml;
            float4 av = make_float4(0.f, 0.f, 0.f, 0.f);
            if (urow < USTEPS)
                av = *reinterpret_cast<const float4*>(
                    g_catall + ((size_t)urow * 32 + b) * 1024 + k0 + (kq << 2));
            int pc = ml ^ (kq << 2);
            As[(kq << 2) + 0][pc] = av.x;
            As[(kq << 2) + 1][pc] = av.y;
            As[(kq << 2) + 2][pc] = av.z;
            As[(kq << 2) + 3][pc] = av.w;
        }
        // B: rows t (enc, d contiguous), transpose to [k][t]
#pragma unroll
        for (int it = 0; it < 2; it++) {
            int s  = tid + it * 256;
            int dq = s & 3;
            int tl = s >> 2;
            int t  = n0 + tl;
            float4 bv = make_float4(0.f, 0.f, 0.f, 0.f);
            if (t < T1)
                bv = *reinterpret_cast<const float4*>(
                    g_h1 + ((size_t)b * T1 + t) * 512 + k0 + (dq << 2));
            int pc = tl ^ (dq << 2);
            Bs[(dq << 2) + 0][pc] = bv.x;
            Bs[(dq << 2) + 1][pc] = bv.y;
            Bs[(dq << 2) + 2][pc] = bv.z;
            Bs[(dq << 2) + 3][pc] = bv.w;
        }
        __syncthreads();

#pragma unroll
        for (int kk = 0; kk < 16; kk++) {
            const int sw = (kk >> 2) << 2;
            float4 a0 = *reinterpret_cast<const float4*>(&As[kk][(ty << 3) ^ sw]);
            float4 a1 = *reinterpret_cast<const float4*>(&As[kk][((ty << 3) + 4) ^ sw]);
            ulonglong2 bp0 = *reinterpret_cast<const ulonglong2*>(&Bs[kk][(tx << 3) ^ sw]);
            ulonglong2 bp1 = *reinterpret_cast<const ulonglong2*>(&Bs[kk][((tx << 3) + 4) ^ sw]);
            ull b0 = bp0.x, b1 = bp0.y, b2 = bp1.x, b3 = bp1.y;
            float av[8] = {a0.x, a0.y, a0.z, a0.w, a1.x, a1.y, a1.z, a1.w};
#pragma unroll
            for (int i = 0; i < 8; i++) {
                ull a2 = pack2(av[i]);
                fma2(acc[i][0], a2, b0);
                fma2(acc[i][1], a2, b1);
                fma2(acc[i][2], a2, b2);
                fma2(acc[i][3], a2, b3);
            }
        }
        __syncthreads();
    }

    const int t0 = n0 + (tx << 3);
#pragma unroll
    for (int i = 0; i < 8; i++) {
        int urow = m0 + (ty << 3) + i;
        if (urow < USTEPS && t0 < T1) {
            float2 p0v = unpack2(acc[i][0]);
            float2 p1v = unpack2(acc[i][1]);
            float2 p2v = unpack2(acc[i][2]);
            float2 p3v = unpack2(acc[i][3]);
            float* sp = g_scoresall + ((size_t)urow * 32 + b) * T1 + t0;
            *reinterpret_cast<float4*>(sp)     = make_float4(p0v.x, p0v.y, p1v.x, p1v.y);
            *reinterpret_cast<float4*>(sp + 4) = make_float4(p2v.x, p2v.y, p3v.x, p3v.y);
        }
    }
}

// ---------------- Batched softmax over 800 (6400 rows), in place ----------------
__global__ void __launch_bounds__(256) sm800_kernel() {
    const int row = blockIdx.x;
    const int tid = threadIdx.x;
    float* sp = g_scoresall + (size_t)row * T1;
    __shared__ float sa[800];
    __shared__ float red[8], red2[8];
    const int w = tid >> 5, lane = tid & 31;

    float m = -1e30f;
    for (int t = tid; t < 800; t += 256) {
        float v = sp[t];
        sa[t] = v;
        m = fmaxf(m, v);
    }
#pragma unroll
    for (int o = 16; o; o >>= 1) m = fmaxf(m, __shfl_xor_sync(0xffffffffu, m, o));
    if (lane == 0) red[w] = m;
    __syncthreads();
    float mm = red[0];
#pragma unroll
    for (int i = 1; i < 8; i++) mm = fmaxf(mm, red[i]);

    float ps = 0.f;
    for (int t = tid; t < 800; t += 256) {
        float e = expf(sa[t] - mm);
        sa[t] = e;
        ps += e;
    }
#pragma unroll
    for (int o = 16; o; o >>= 1) ps += __shfl_xor_sync(0xffffffffu, ps, o);
    if (lane == 0) red2[w] = ps;
    __syncthreads();
    float sum = 0.f;
#pragma unroll
    for (int i = 0; i < 8; i++) sum += red2[i];
    const float inv = 1.f / sum;

    for (int t = tid; t < 800; t += 256) sp[t] = sa[t] * inv;
}

// ---------------- Batched ctx: per b, alpha[200,800] @ enc_b[800,512] ----------------
__global__ void __launch_bounds__(256, 2) ctx_gemm_kernel() {
    __shared__ __align__(16) float As[16][128];
    __shared__ __align__(16) float Bs[16][128];
    const int tid = threadIdx.x;
    const int n0 = blockIdx.x * 128;
    const int m0 = blockIdx.y * 128;   // row = step u
    const int b  = blockIdx.z;
    const int tx = tid & 15;
    const int ty = tid >> 4;

    ull acc[8][4];
#pragma unroll
    for (int i = 0; i < 8; i++)
#pragma unroll
        for (int j = 0; j < 4; j++) acc[i][j] = 0ull;

    for (int k0 = 0; k0 < 800; k0 += 16) {
#pragma unroll
        for (int it = 0; it < 2; it++) {
            int s  = tid + it * 256;
            int kq = s & 3;
            int ml = s >> 2;
            int u  = m0 + ml;
            float4 av = make_float4(0.f, 0.f, 0.f, 0.f);
            if (u < USTEPS)
                av = *reinterpret_cast<const float4*>(
                    g_scoresall + ((size_t)u * 32 + b) * T1 + k0 + (kq << 2));
            As[(kq << 2) + 0][ml] = av.x;
            As[(kq << 2) + 1][ml] = av.y;
            As[(kq << 2) + 2][ml] = av.z;
            As[(kq << 2) + 3][ml] = av.w;
        }
#pragma unroll
        for (int it = 0; it < 2; it++) {
            int s  = tid + it * 256;
            int cq = s & 31;
            int kr = s >> 5;
            *reinterpret_cast<float4*>(&Bs[kr][cq << 2]) =
                *reinterpret_cast<const float4*>(
                    g_h1 + ((size_t)b * T1 + k0 + kr) * 512 + n0 + (cq << 2));
        }
        __syncthreads();

#pragma unroll
        for (int kk = 0; kk < 16; kk++) {
            float4 a0 = *reinterpret_cast<const float4*>(&As[kk][ty << 3]);
            float4 a1 = *reinterpret_cast<const float4*>(&As[kk][(ty << 3) + 4]);
            ulonglong2 bp0 = *reinterpret_cast<const ulonglong2*>(&Bs[kk][(tx << 3)]);
            ulonglong2 bp1 = *reinterpret_cast<const ulonglong2*>(&Bs[kk][(tx << 3) + 4]);
            ull b0 = bp0.x, b1 = bp0.y, b2 = bp1.x, b3 = bp1.y;
            float av[8] = {a0.x, a0.y, a0.z, a0.w, a1.x, a1.y, a1.z, a1.w};
#pragma unroll
            for (int i = 0; i < 8; i++) {
                ull a2 = pack2(av[i]);
                fma2(acc[i][0], a2, b0);
                fma2(acc[i][1], a2, b1);
                fma2(acc[i][2], a2, b2);
                fma2(acc[i][3], a2, b3);
            }
        }
        __syncthreads();
    }

#pragma unroll
    for (int i = 0; i < 8; i++) {
        int u = m0 + (ty << 3) + i;
        if (u < USTEPS) {
            float2 p0v = unpack2(acc[i][0]);
            float2 p1v = unpack2(acc[i][1]);
            float2 p2v = unpack2(acc[i][2]);
            float2 p3v = unpack2(acc[i][3]);
            float* cp = g_catall + ((size_t)u * 32 + b) * 1024 + 512 + n0 + (tx << 3);
            *reinterpret_cast<float4*>(cp)     = make_float4(p0v.x, p0v.y, p1v.x, p1v.y);
            *reinterpret_cast<float4*>(cp + 4) = make_float4(p2v.x, p2v.y, p3v.x, p3v.y);
        }
    }
}

// ---------------- Batched FC: logits[6400,1000] = cat[6400,1024] @ fc_w + fc_b ----------------
__global__ void __launch_bounds__(256, 2) fc_big_kernel(const float* __restrict__ fw,
                                                        const float* __restrict__ fb) {
    __shared__ __align__(16) float As[16][128];
    __shared__ __align__(16) float Bs[16][128];
    const int tid = threadIdx.x;
    const int n0 = blockIdx.x * 128;
    const int m0 = blockIdx.y * 128;
    const int tx = tid & 15;
    const int ty = tid >> 4;

    ull acc[8][4];
#pragma unroll
    for (int i = 0; i < 8; i++)
#pragma unroll
        for (int j = 0; j < 4; j++) acc[i][j] = 0ull;

    for (int p0 = 0; p0 < 1024; p0 += 16) {
#pragma unroll
        for (int it = 0; it < 2; it++) {
            int s  = tid + it * 256;
            int kq = s & 3;
            int ml = s >> 2;
            float4 av = *reinterpret_cast<const float4*>(
                g_catall + ((size_t)(m0 + ml)) * 1024 + p0 + (kq << 2));
            As[(kq << 2) + 0][ml] = av.x;
            As[(kq << 2) + 1][ml] = av.y;
            As[(kq << 2) + 2][ml] = av.z;
            As[(kq << 2) + 3][ml] = av.w;
        }
#pragma unroll
        for (int it = 0; it < 2; it++) {
            int s  = tid + it * 256;
            int cq = s & 31;
            int kr = s >> 5;
            int c  = n0 + (cq << 2);
            float4 v = make_float4(0.f, 0.f, 0.f, 0.f);
            if (c < 1000)
                v = *reinterpret_cast<const float4*>(fw + (size_t)(p0 + kr) * 1000 + c);
            *reinterpret_cast<float4*>(&Bs[kr][cq << 2]) = v;
        }
        __syncthreads();

#pragma unroll
        for (int kk = 0; kk < 16; kk++) {
            float4 a0 = *reinterpret_cast<const float4*>(&As[kk][ty << 3]);
            float4 a1 = *reinterpret_cast<const float4*>(&As[kk][(ty << 3) + 4]);
            ulonglong2 bp0 = *reinterpret_cast<const ulonglong2*>(&Bs[kk][(tx << 3)]);
            ulonglong2 bp1 = *reinterpret_cast<const ulonglong2*>(&Bs[kk][(tx << 3) + 4]);
            ull b0 = bp0.x, b1 = bp0.y, b2 = bp1.x, b3 = bp1.y;
            float av[8] = {a0.x, a0.y, a0.z, a0.w, a1.x, a1.y, a1.z, a1.w};
#pragma unroll
            for (int i = 0; i < 8; i++) {
                ull a2 = pack2(av[i]);
                fma2(acc[i][0], a2, b0);
                fma2(acc[i][1], a2, b1);
                fma2(acc[i][2], a2, b2);
                fma2(acc[i][3], a2, b3);
            }
        }
        __syncthreads();
    }

    const int c0 = n0 + (tx << 3);
    float bias[8];
#pragma unroll
    for (int j = 0; j < 8; j++) bias[j] = (c0 + j < 1000) ? fb[c0 + j] : 0.f;
#pragma unroll
    for (int i = 0; i < 8; i++) {
        int m = m0 + (ty << 3) + i;
        float2 p0v = unpack2(acc[i][0]);
        float2 p1v = unpack2(acc[i][1]);
        float2 p2v = unpack2(acc[i][2]);
        float2 p3v = unpack2(acc[i][3]);
        float4 r0 = make_float4(p0v.x + bias[0], p0v.y + bias[1], p1v.x + bias[2], p1v.y + bias[3]);
        float4 r1 = make_float4(p2v.x + bias[4], p2v.y + bias[5], p3v.x + bias[6], p3v.y + bias[7]);
        float* lp = g_logitsall + (size_t)m * 1000;
        if (c0 < 1000)     *reinterpret_cast<float4*>(lp + c0)     = r0;
        if (c0 + 4 < 1000) *reinterpret_cast<float4*>(lp + c0 + 4) = r1;
    }
}

// ---------------- Batched output softmax ----------------
__global__ void __launch_bounds__(256) outsm_all_kernel(float* __restrict__ out) {
    const int m = blockIdx.x;            // m = u*32 + b
    const int u = m >> 5, b = m & 31;
    const int tid = threadIdx.x;
    __shared__ float sh[1000];
    __shared__ float red[8], red2[8];
    const int w = tid >> 5, lane = tid & 31;
    const float* lp = g_logitsall + (size_t)m * 1000;

    float mx = -1e30f;
    for (int c = tid; c < 1000; c += 256) {
        float v = lp[c];
        sh[c] = v;
        mx = fmaxf(mx, v);
    }
#pragma unroll
    for (int o = 16; o; o >>= 1) mx = fmaxf(mx, __shfl_xor_sync(0xffffffffu, mx, o));
    if (lane == 0) red[w] = mx;
    __syncthreads();
    float mm = red[0];
#pragma unroll
    for (int i = 1; i < 8; i++) mm = fmaxf(mm, red[i]);

    float ps = 0.f;
    for (int c = tid; c < 1000; c += 256) {
        float e = expf(sh[c] - mm);
        sh[c] = e;
        ps += e;
    }
#pragma unroll
    for (int o = 16; o; o >>= 1) ps += __shfl_xor_sync(0xffffffffu, ps, o);
    if (lane == 0) red2[w] = ps;
    __syncthreads();
    float sum = 0.f;
#pragma unroll
    for (int i = 0; i < 8; i++) sum += red2[i];
    const float inv = 1.f / sum;

    float* op = out + ((size_t)b * USTEPS + u) * VOCABN;
    for (int c = tid; c < 1000; c += 256) op[c] = sh[c] * inv;
}

// ---------------- launch ----------------
extern "C" void kernel_launch(void* const* d_in, const int* in_sizes, int n_in,
                              void* d_out, int out_size) {
    const float* x        = (const float*)d_in[0];
    const int*   y        = (const int*)  d_in[1];
    const float* bn_gamma = (const float*)d_in[2];
    const float* bn_beta  = (const float*)d_in[3];
    const float* conv0_w  = (const float*)d_in[4];
    const float* conv0_b  = (const float*)d_in[5];
    const float* tcr_w    = (const float*)d_in[6];
    const float* tcr_b    = (const float*)d_in[7];
    const float* gru_k    = (const float*)d_in[8];
    const float* gru_rk   = (const float*)d_in[9];
    const float* gru_b    = (const float*)d_in[10];
    const float* fc_w     = (const float*)d_in[11];
    const float* fc_b     = (const float*)d_in[12];
    float* out = (float*)d_out;

    float *h1, *h2;
    cudaGetSymbolAddress((void**)&h1, g_h1);
    cudaGetSymbolAddress((void**)&h2, g_h2);

    // ---- encoder ----
    bn_stats_kernel<<<80, 256>>>(x, bn_gamma, bn_beta);
    zero_h_kernel<<<32, 512>>>();

    dim3 cgrid(4, 200);
    conv5x_kernel<80, 1600, 800, 2, 1, true,  false><<<cgrid, 256>>>(x,  conv0_w, conv0_b, h1);
    const size_t WSZ = (size_t)5 * 512 * 512;
    conv5x_kernel<512, 800, 800, 1, 2, false, true><<<cgrid, 256>>>(h1, tcr_w + 0 * WSZ, tcr_b + 0 * 512, h2);
    conv5x_kernel<512, 800, 800, 1, 2, false, true><<<cgrid, 256>>>(h2, tcr_w + 1 * WSZ, tcr_b + 1 * 512, h1);
    conv5x_kernel<512, 800, 800, 1, 2, false, true><<<cgrid, 256>>>(h1, tcr_w + 2 * WSZ, tcr_b + 2 * 512, h2);
    conv5x_kernel<512, 800, 800, 1, 2, false, true><<<cgrid, 256>>>(h2, tcr_w + 3 * WSZ, tcr_b + 3 * 512, h1);
    // enc lives in g_h1

    // ---- pure GRU recurrence: 2 tiny kernels per step ----
    dim3 pgrid(12, 4);
    for (int u = 0; u < USTEPS; u++) {
        gru_part_kernel<<<pgrid, 256>>>(gru_rk, u);
        gru_gates_kernel<<<32, 512>>>(y, gru_k, gru_b, u);
    }

    // ---- batched tail ----
    dim3 sgrid(7, 2, 32);
    scores_gemm_kernel<<<sgrid, 256>>>();
    sm800_kernel<<<USTEPS * B_, 256>>>();
    dim3 xgrid(4, 2, 32);
    ctx_gemm_kernel<<<xgrid, 256>>>();
    dim3 fgrid(8, 50);
    fc_big_kernel<<<fgrid, 256>>>(fc_w, fc_b);
    outsm_all_kernel<<<USTEPS * B_, 256>>>(out);
}

// round 9
// speedup vs baseline: 8.7048x; 1.4946x over previous
#include <cuda_runtime.h>
#include <cuda_bf16.h>
#include <cstdint>
#include <math.h>

typedef unsigned long long ull;
typedef unsigned int uint;

#define B_     32
#define T0     1600
#define C0     80
#define T1     800
#define D_     512
#define VOCABN 1000
#define HIDN   512
#define USTEPS 200
#define EPSV   1e-3f

// ---------------- scratch (static device globals; no allocation) ----------------
__device__ float g_bn[160];
__device__ float g_h1[B_ * T1 * D_];                // fp32 activations (enc ends here)
__device__ float g_h2[B_ * T1 * D_];
__device__ float g_hstate[2][B_ * HIDN];
__device__ float g_mhp[4][B_ * 1536];
__device__ float g_scoresall[USTEPS * B_ * T1];
__device__ float g_catall[USTEPS * B_ * 1024];
__device__ float g_logitsall[USTEPS * B_ * VOCABN];
// bf16 split activations (ping-pong) and split transposed weights
__device__ __nv_bfloat16 g_shi0[B_ * T1 * D_];
__device__ __nv_bfloat16 g_slo0[B_ * T1 * D_];
__device__ __nv_bfloat16 g_shi1[B_ * T1 * D_];
__device__ __nv_bfloat16 g_slo1[B_ * T1 * D_];
__device__ __nv_bfloat16 g_wt_hi[4 * 512 * 2560];   // [l][n][kin]
__device__ __nv_bfloat16 g_wt_lo[4 * 512 * 2560];

// ---------------- packed f32x2 helpers (FFMA2) ----------------
__device__ __forceinline__ void fma2(ull& d, ull a, ull b) {
    asm("fma.rn.f32x2 %0, %1, %2, %0;" : "+l"(d) : "l"(a), "l"(b));
}
__device__ __forceinline__ ull pack2(float x) {
    ull r;
    asm("mov.b64 %0, {%1, %1};" : "=l"(r) : "f"(x));
    return r;
}
__device__ __forceinline__ float2 unpack2(ull v) {
    float2 f;
    asm("mov.b64 {%0, %1}, %2;" : "=f"(f.x), "=f"(f.y) : "l"(v));
    return f;
}

// ---------------- bf16 split helpers ----------------
__device__ __forceinline__ void split4(float4 v, uint2& hi, uint2& lo) {
    __nv_bfloat16 h0 = __float2bfloat16(v.x), h1 = __float2bfloat16(v.y);
    __nv_bfloat16 h2 = __float2bfloat16(v.z), h3 = __float2bfloat16(v.w);
    __nv_bfloat16 l0 = __float2bfloat16(v.x - __bfloat162float(h0));
    __nv_bfloat16 l1 = __float2bfloat16(v.y - __bfloat162float(h1));
    __nv_bfloat16 l2 = __float2bfloat16(v.z - __bfloat162float(h2));
    __nv_bfloat16 l3 = __float2bfloat16(v.w - __bfloat162float(h3));
    hi.x = (uint)__bfloat16_as_ushort(h0) | ((uint)__bfloat16_as_ushort(h1) << 16);
    hi.y = (uint)__bfloat16_as_ushort(h2) | ((uint)__bfloat16_as_ushort(h3) << 16);
    lo.x = (uint)__bfloat16_as_ushort(l0) | ((uint)__bfloat16_as_ushort(l1) << 16);
    lo.y = (uint)__bfloat16_as_ushort(l2) | ((uint)__bfloat16_as_ushort(l3) << 16);
}
__device__ __forceinline__ void split2(float x, float y, uint& hi, uint& lo) {
    __nv_bfloat16 hx = __float2bfloat16(x), hy = __float2bfloat16(y);
    __nv_bfloat16 lx = __float2bfloat16(x - __bfloat162float(hx));
    __nv_bfloat16 ly = __float2bfloat16(y - __bfloat162float(hy));
    hi = (uint)__bfloat16_as_ushort(hx) | ((uint)__bfloat16_as_ushort(hy) << 16);
    lo = (uint)__bfloat16_as_ushort(lx) | ((uint)__bfloat16_as_ushort(ly) << 16);
}

// ---------------- mma.sync / ldmatrix helpers (sm_80+ portable) ----------------
__device__ __forceinline__ uint32_t smem_to_u32(const void* p) {
    uint32_t a;
    asm("{ .reg .u64 t; cvta.to.shared.u64 t, %1; cvt.u32.u64 %0, t; }" : "=r"(a) : "l"(p));
    return a;
}
__device__ __forceinline__ void mma_bf16(float* d, const uint32_t* a, const uint32_t* b) {
    asm volatile(
        "mma.sync.aligned.m16n8k16.row.col.f32.bf16.bf16.f32 "
        "{%0,%1,%2,%3}, {%4,%5,%6,%7}, {%8,%9}, {%0,%1,%2,%3};"
        : "+f"(d[0]), "+f"(d[1]), "+f"(d[2]), "+f"(d[3])
        : "r"(a[0]), "r"(a[1]), "r"(a[2]), "r"(a[3]), "r"(b[0]), "r"(b[1]));
}
__device__ __forceinline__ void ldsm4(uint32_t* r, uint32_t addr) {
    asm volatile("ldmatrix.sync.aligned.m8n8.x4.shared.b16 {%0,%1,%2,%3}, [%4];"
                 : "=r"(r[0]), "=r"(r[1]), "=r"(r[2]), "=r"(r[3]) : "r"(addr));
}

// ---------------- BatchNorm statistics ----------------
__global__ void __launch_bounds__(256) bn_stats_kernel(const float* __restrict__ x,
                                                       const float* __restrict__ gamma,
                                                       const float* __restrict__ beta) {
    const int c = blockIdx.x;
    const int tid = threadIdx.x;
    const int N = B_ * T0;
    float s = 0.f, sq = 0.f;
    for (int i = tid; i < N; i += 256) {
        float v = x[(size_t)i * C0 + c];
        s += v; sq += v * v;
    }
    __shared__ float rs[256], rq[256];
    rs[tid] = s; rq[tid] = sq;
    __syncthreads();
    for (int o = 128; o > 0; o >>= 1) {
        if (tid < o) { rs[tid] += rs[tid + o]; rq[tid] += rq[tid + o]; }
        __syncthreads();
    }
    if (tid == 0) {
        float mean = rs[0] / (float)N;
        float var  = rq[0] / (float)N - mean * mean;
        float sc   = gamma[c] * rsqrtf(var + EPSV);
        g_bn[c]      = sc;
        g_bn[80 + c] = beta[c] - mean * sc;
    }
}

__global__ void __launch_bounds__(512) zero_h_kernel() {
    int i = blockIdx.x * blockDim.x + threadIdx.x;
    if (i < B_ * HIDN) g_hstate[0][i] = 0.f;
}

// ---------------- weight transpose + bf16 split: tcr_w [l][kin][512] -> wt[l][n][kin] ----------------
__global__ void __launch_bounds__(256) wsplit_kernel(const float* __restrict__ tcr_w) {
    __shared__ float tile[32][33];
    const int l  = blockIdx.z;
    const int k0 = blockIdx.x * 32;
    const int n0 = blockIdx.y * 32;
    const int tx = threadIdx.x, ty = threadIdx.y;   // 32 x 8
#pragma unroll
    for (int j = 0; j < 32; j += 8)
        tile[ty + j][tx] = tcr_w[((size_t)l * 2560 + k0 + ty + j) * 512 + n0 + tx];
    __syncthreads();
#pragma unroll
    for (int j = 0; j < 32; j += 8) {
        float v = tile[tx][ty + j];
        size_t di = ((size_t)l * 512 + n0 + ty + j) * 2560 + k0 + tx;
        __nv_bfloat16 h = __float2bfloat16(v);
        g_wt_hi[di] = h;
        g_wt_lo[di] = __float2bfloat16(v - __bfloat162float(h));
    }
}

// ---------------- conv0: implicit-im2col SGEMM 128x128x32 FFMA2 (+ split epilogue) ----------------
template<int CIN, int TIN, int TOUT, int STRIDE, int PADL, bool FUSE_BN, bool RESID, bool SPLIT>
__global__ void __launch_bounds__(256, 2) conv5x_kernel(const float* __restrict__ in,
                                                        const float* __restrict__ w,
                                                        const float* __restrict__ bias,
                                                        float* __restrict__ out,
                                                        __nv_bfloat16* __restrict__ ohi,
                                                        __nv_bfloat16* __restrict__ olo) {
    __shared__ __align__(16) float As[32][128];
    __shared__ __align__(16) float Bs[32][128];
    __shared__ __align__(16) float s_bn[160];

    const int tid = threadIdx.x;
    if (FUSE_BN && tid < 160) s_bn[tid] = g_bn[tid];

    const int n0 = blockIdx.x * 128;
    const int m0 = blockIdx.y * 128;
    const int tx = tid & 15;
    const int ty = tid >> 4;

    ull acc[4][8];
#pragma unroll
    for (int i = 0; i < 4; i++)
#pragma unroll
        for (int j = 0; j < 8; j++) acc[i][j] = 0ull;

    __syncthreads();

    const int KIN = 5 * CIN;
    for (int p0 = 0; p0 < KIN; p0 += 32) {
#pragma unroll
        for (int it = 0; it < 4; it++) {
            int s  = tid + it * 256;
            int kq = s & 7;
            int ml = s >> 3;
            int p  = p0 + (kq << 2);
            int k  = p / CIN;
            int ci = p - k * CIN;
            int m  = m0 + ml;
            int bb = m / TOUT;
            int t  = m - bb * TOUT;
            int tin = t * STRIDE - PADL + k;
            float4 av = make_float4(0.f, 0.f, 0.f, 0.f);
            if (tin >= 0 && tin < TIN && p < KIN) {
                av = *reinterpret_cast<const float4*>(in + ((size_t)bb * TIN + tin) * CIN + ci);
                if (FUSE_BN) {
                    float4 sc = *reinterpret_cast<const float4*>(&s_bn[ci]);
                    float4 sh = *reinterpret_cast<const float4*>(&s_bn[80 + ci]);
                    av.x = av.x * sc.x + sh.x;
                    av.y = av.y * sc.y + sh.y;
                    av.z = av.z * sc.z + sh.z;
                    av.w = av.w * sc.w + sh.w;
                }
            }
            int pc = ml ^ (kq << 2);
            As[(kq << 2) + 0][pc] = av.x;
            As[(kq << 2) + 1][pc] = av.y;
            As[(kq << 2) + 2][pc] = av.z;
            As[(kq << 2) + 3][pc] = av.w;
        }
#pragma unroll
        for (int it = 0; it < 4; it++) {
            int s  = tid + it * 256;
            int cq = s & 31;
            int kr = s >> 5;
            float4 v = make_float4(0.f, 0.f, 0.f, 0.f);
            if (p0 + kr < KIN)
                v = *reinterpret_cast<const float4*>(w + (size_t)(p0 + kr) * 512 + n0 + (cq << 2));
            *reinterpret_cast<float4*>(&Bs[kr][cq << 2]) = v;
        }
        __syncthreads();

#pragma unroll
        for (int kk = 0; kk < 32; kk++) {
            const int sw = (kk >> 2) << 2;
            ulonglong2 ap0 = *reinterpret_cast<const ulonglong2*>(&As[kk][(ty << 3) ^ sw]);
            ulonglong2 ap1 = *reinterpret_cast<const ulonglong2*>(&As[kk][((ty << 3) + 4) ^ sw]);
            ull ap[4] = {ap0.x, ap0.y, ap1.x, ap1.y};
            float4 bA = *reinterpret_cast<const float4*>(&Bs[kk][tx << 2]);
            float4 bB = *reinterpret_cast<const float4*>(&Bs[kk][64 + (tx << 2)]);
            ull bd[8];
            bd[0] = pack2(bA.x); bd[1] = pack2(bA.y); bd[2] = pack2(bA.z); bd[3] = pack2(bA.w);
            bd[4] = pack2(bB.x); bd[5] = pack2(bB.y); bd[6] = pack2(bB.z); bd[7] = pack2(bB.w);
#pragma unroll
            for (int mp = 0; mp < 4; mp++)
#pragma unroll
                for (int n = 0; n < 8; n++) fma2(acc[mp][n], ap[mp], bd[n]);
        }
        __syncthreads();
    }

    const int c0 = n0 + (tx << 2);
    const int c1 = n0 + 64 + (tx << 2);
    const float4 bias0 = *reinterpret_cast<const float4*>(bias + c0);
    const float4 bias1 = *reinterpret_cast<const float4*>(bias + c1);
    float2 u0[4][4], u1[4][4];
#pragma unroll
    for (int mp = 0; mp < 4; mp++)
#pragma unroll
        for (int n = 0; n < 4; n++) {
            u0[mp][n] = unpack2(acc[mp][n]);
            u1[mp][n] = unpack2(acc[mp][4 + n]);
        }
#pragma unroll
    for (int i = 0; i < 8; i++) {
        const int mp = i >> 1;
        const bool hi = i & 1;
        int m = m0 + (ty << 3) + i;
        float4 r0, r1;
        r0.x = fmaxf((hi ? u0[mp][0].y : u0[mp][0].x) + bias0.x, 0.f);
        r0.y = fmaxf((hi ? u0[mp][1].y : u0[mp][1].x) + bias0.y, 0.f);
        r0.z = fmaxf((hi ? u0[mp][2].y : u0[mp][2].x) + bias0.z, 0.f);
        r0.w = fmaxf((hi ? u0[mp][3].y : u0[mp][3].x) + bias0.w, 0.f);
        r1.x = fmaxf((hi ? u1[mp][0].y : u1[mp][0].x) + bias1.x, 0.f);
        r1.y = fmaxf((hi ? u1[mp][1].y : u1[mp][1].x) + bias1.y, 0.f);
        r1.z = fmaxf((hi ? u1[mp][2].y : u1[mp][2].x) + bias1.z, 0.f);
        r1.w = fmaxf((hi ? u1[mp][3].y : u1[mp][3].x) + bias1.w, 0.f);
        if (RESID) {
            float4 e0 = *reinterpret_cast<const float4*>(in + (size_t)m * CIN + c0);
            float4 e1 = *reinterpret_cast<const float4*>(in + (size_t)m * CIN + c1);
            r0.x += e0.x; r0.y += e0.y; r0.z += e0.z; r0.w += e0.w;
            r1.x += e1.x; r1.y += e1.y; r1.z += e1.z; r1.w += e1.w;
        }
        *reinterpret_cast<float4*>(out + (size_t)m * 512 + c0) = r0;
        *reinterpret_cast<float4*>(out + (size_t)m * 512 + c1) = r1;
        if (SPLIT) {
            uint2 h4, l4;
            split4(r0, h4, l4);
            *reinterpret_cast<uint2*>(ohi + (size_t)m * 512 + c0) = h4;
            *reinterpret_cast<uint2*>(olo + (size_t)m * 512 + c0) = l4;
            split4(r1, h4, l4);
            *reinterpret_cast<uint2*>(ohi + (size_t)m * 512 + c1) = h4;
            *reinterpret_cast<uint2*>(olo + (size_t)m * 512 + c1) = l4;
        }
    }
}

// ---------------- tcr conv layer on mma.sync (bf16 3-product split) ----------------
// CTA 128x128, 8 warps (4m x 2n), warp 32x64 = 2 mtiles x 8 ntiles of m16n8k16.
// A[m][kin] split hi/lo, B = weights [n][kin] split hi/lo. K-chunk 32 (80 chunks).
// smem rows padded to 40 bf16 (80 B). B stored [n][k] -> NON-trans ldmatrix gives the
// .col B fragment (lane j: n=j>>2, k=2*(j%4)+h) directly.
#define ASTR 40
template<bool SPLIT>
__global__ void __launch_bounds__(256, 2) tcr_mma_kernel(const __nv_bfloat16* __restrict__ ahi,
                                                         const __nv_bfloat16* __restrict__ alo,
                                                         const __nv_bfloat16* __restrict__ whi,
                                                         const __nv_bfloat16* __restrict__ wlo,
                                                         const float* __restrict__ resid_in,
                                                         const float* __restrict__ bias,
                                                         float* __restrict__ out,
                                                         __nv_bfloat16* __restrict__ ohi,
                                                         __nv_bfloat16* __restrict__ olo) {
    __shared__ __align__(16) __nv_bfloat16 sAh[128 * ASTR];
    __shared__ __align__(16) __nv_bfloat16 sAl[128 * ASTR];
    __shared__ __align__(16) __nv_bfloat16 sBh[128 * ASTR];
    __shared__ __align__(16) __nv_bfloat16 sBl[128 * ASTR];

    const int tid = threadIdx.x;
    const int wid = tid >> 5, lane = tid & 31;
    const int n0 = blockIdx.x * 128;
    const int m0 = blockIdx.y * 128;
    const int warp_m = (wid >> 1) << 5;    // 0,32,64,96
    const int warp_n = (wid & 1) << 6;     // 0,64

    float acc[2][8][4];
#pragma unroll
    for (int i = 0; i < 2; i++)
#pragma unroll
        for (int j = 0; j < 8; j++)
#pragma unroll
            for (int r = 0; r < 4; r++) acc[i][j][r] = 0.f;

    const int lq = tid & 3;       // 16B quad within 64B row-chunk
    const int lrow = tid >> 2;    // 0..63

    // ldmatrix per-lane base addresses (bytes)
    const uint32_t aAddrH = smem_to_u32(sAh) + (warp_m + (lane & 15)) * 80 + (lane >> 4) * 16;
    const uint32_t aAddrL = smem_to_u32(sAl) + (warp_m + (lane & 15)) * 80 + (lane >> 4) * 16;
    const int browoff = warp_n + (lane & 7) + ((lane >> 4) & 1) * 8;
    const uint32_t bAddrH = smem_to_u32(sBh) + browoff * 80 + ((lane >> 3) & 1) * 16;
    const uint32_t bAddrL = smem_to_u32(sBl) + browoff * 80 + ((lane >> 3) & 1) * 16;

    for (int c = 0; c < 80; c++) {
        const int tap = c >> 4;
        const int ci0 = (c & 15) << 5;
        // ---- load A (hi/lo): 128 rows x 32 bf16 ----
#pragma unroll
        for (int it = 0; it < 2; it++) {
            int ml = lrow + it * 64;
            int m  = m0 + ml;
            int bb = m / T1;
            int t  = m - bb * T1;
            int tin = t + tap - 2;
            uint4 vh = make_uint4(0, 0, 0, 0), vl = make_uint4(0, 0, 0, 0);
            if (tin >= 0 && tin < T1) {
                size_t src = ((size_t)bb * T1 + tin) * 512 + ci0 + lq * 8;
                vh = *reinterpret_cast<const uint4*>(ahi + src);
                vl = *reinterpret_cast<const uint4*>(alo + src);
            }
            *reinterpret_cast<uint4*>(&sAh[ml * ASTR + lq * 8]) = vh;
            *reinterpret_cast<uint4*>(&sAl[ml * ASTR + lq * 8]) = vl;
        }
        // ---- load B (hi/lo): 128 n-rows x 32 bf16 ----
#pragma unroll
        for (int it = 0; it < 2; it++) {
            int nl = lrow + it * 64;
            size_t src = (size_t)(n0 + nl) * 2560 + c * 32 + lq * 8;
            *reinterpret_cast<uint4*>(&sBh[nl * ASTR + lq * 8]) = *reinterpret_cast<const uint4*>(whi + src);
            *reinterpret_cast<uint4*>(&sBl[nl * ASTR + lq * 8]) = *reinterpret_cast<const uint4*>(wlo + src);
        }
        __syncthreads();

#pragma unroll
        for (int s = 0; s < 2; s++) {
            uint32_t ah[2][4], al[2][4];
            ldsm4(ah[0], aAddrH + s * 32);
            ldsm4(ah[1], aAddrH + s * 32 + 16 * 80);
            ldsm4(al[0], aAddrL + s * 32);
            ldsm4(al[1], aAddrL + s * 32 + 16 * 80);
#pragma unroll
            for (int jj = 0; jj < 4; jj++) {
                uint32_t bh[4], bl[4];
                ldsm4(bh, bAddrH + s * 32 + jj * 16 * 80);
                ldsm4(bl, bAddrL + s * 32 + jj * 16 * 80);
#pragma unroll
                for (int i = 0; i < 2; i++) {
                    mma_bf16(acc[i][2 * jj],     ah[i], bh);
                    mma_bf16(acc[i][2 * jj],     ah[i], bl);
                    mma_bf16(acc[i][2 * jj],     al[i], bh);
                    mma_bf16(acc[i][2 * jj + 1], ah[i], bh + 2);
                    mma_bf16(acc[i][2 * jj + 1], ah[i], bl + 2);
                    mma_bf16(acc[i][2 * jj + 1], al[i], bh + 2);
                }
            }
        }
        __syncthreads();
    }

    // ---- epilogue: bias + relu + residual (+ split) ----
    const int r0 = lane >> 2;
    const int cc = (lane & 3) * 2;
#pragma unroll
    for (int i = 0; i < 2; i++) {
        int mrow = m0 + warp_m + i * 16 + r0;
#pragma unroll
        for (int j = 0; j < 8; j++) {
            int col = n0 + warp_n + j * 8 + cc;
            float2 b2 = *reinterpret_cast<const float2*>(bias + col);
#pragma unroll
            for (int half = 0; half < 2; half++) {
                int m = mrow + half * 8;
                float va = acc[i][j][half * 2 + 0];
                float vb = acc[i][j][half * 2 + 1];
                float2 e = *reinterpret_cast<const float2*>(resid_in + (size_t)m * 512 + col);
                float2 v;
                v.x = fmaxf(va + b2.x, 0.f) + e.x;
                v.y = fmaxf(vb + b2.y, 0.f) + e.y;
                *reinterpret_cast<float2*>(out + (size_t)m * 512 + col) = v;
                if (SPLIT) {
                    uint h2, l2;
                    split2(v.x, v.y, h2, l2);
                    *reinterpret_cast<uint*>(ohi + (size_t)m * 512 + col) = h2;
                    *reinterpret_cast<uint*>(olo + (size_t)m * 512 + col) = l2;
                }
            }
        }
    }
}

// ---------------- Recurrence kernel A: mh partials (k-split GEMM) ----------------
__global__ void __launch_bounds__(256) gru_part_kernel(const float* __restrict__ grk, int u) {
    __shared__ float Hs[16][33];
    __shared__ __align__(16) float Ws[16][128];
    const float* h = g_hstate[u & 1];
    const int tid = threadIdx.x;
    const int n0 = blockIdx.x * 128;
    const int kb = blockIdx.y * 128;
    const int nx = tid & 31;
    const int my = tid >> 5;

    ull acc[4][2];
#pragma unroll
    for (int i = 0; i < 4; i++) { acc[i][0] = 0ull; acc[i][1] = 0ull; }

    for (int k0 = 0; k0 < 128; k0 += 16) {
#pragma unroll
        for (int it = 0; it < 2; it++) {
            int e = tid + it * 256;
            int kk = e & 15, m = e >> 4;
            Hs[kk][m] = h[m * 512 + kb + k0 + kk];
        }
#pragma unroll
        for (int it = 0; it < 2; it++) {
            int s = tid + it * 256;
            int cq = s & 31, kr = s >> 5;
            *reinterpret_cast<float4*>(&Ws[kr][cq << 2]) =
                *reinterpret_cast<const float4*>(grk + (size_t)(kb + k0 + kr) * 1536 + n0 + (cq << 2));
        }
        __syncthreads();
#pragma unroll
        for (int kk = 0; kk < 16; kk++) {
            ulonglong2 bp = *reinterpret_cast<const ulonglong2*>(&Ws[kk][nx << 2]);
#pragma unroll
            for (int i = 0; i < 4; i++) {
                ull ad = pack2(Hs[kk][(my << 2) + i]);
                fma2(acc[i][0], ad, bp.x);
                fma2(acc[i][1], ad, bp.y);
            }
        }
        __syncthreads();
    }
    float* outp = g_mhp[blockIdx.y];
#pragma unroll
    for (int i = 0; i < 4; i++) {
        float2 v0 = unpack2(acc[i][0]);
        float2 v1 = unpack2(acc[i][1]);
        *reinterpret_cast<float4*>(&outp[((my << 2) + i) * 1536 + n0 + (nx << 2)]) =
            make_float4(v0.x, v0.y, v1.x, v1.y);
    }
}

// ---------------- Recurrence kernel B: sum partials + GRU gates ----------------
__global__ void __launch_bounds__(512) gru_gates_kernel(const int* __restrict__ y,
                                                        const float* __restrict__ gk,
                                                        const float* __restrict__ gb,
                                                        int u) {
    const int b = blockIdx.x;
    const int j = threadIdx.x;
    float hz = 0.f, hr = 0.f, hh = 0.f;
#pragma unroll
    for (int c = 0; c < 4; c++) {
        const float* p = g_mhp[c] + b * 1536;
        hz += p[j];
        hr += p[512 + j];
        hh += p[1024 + j];
    }
    const float* bi = gb;
    const float* br = gb + 1536;
    const int tok   = y[b * 201 + u];
    const float* gx = gk + (size_t)tok * 1536;
    float xz = gx[j]        + bi[j];
    float xr = gx[512 + j]  + bi[512 + j];
    float xh = gx[1024 + j] + bi[1024 + j];
    hz += br[j];
    hr += br[512 + j];
    hh += br[1024 + j];
    float z = 1.f / (1.f + expf(-(xz + hz)));
    float r = 1.f / (1.f + expf(-(xr + hr)));
    float cand = tanhf(xh + r * hh);
    float hold = g_hstate[u & 1][b * 512 + j];
    float hn = z * hold + (1.f - z) * cand;
    g_hstate[(u + 1) & 1][b * 512 + j] = hn;
    g_catall[((size_t)u * 32 + b) * 1024 + j] = hn;
}

// ---------------- Batched scores GEMM: per b, S[200,800] = H[200,512] @ enc_b^T ----------------
__global__ void __launch_bounds__(256, 2) scores_gemm_kernel() {
    __shared__ __align__(16) float As[16][128];
    __shared__ __align__(16) float Bs[16][128];
    const int tid = threadIdx.x;
    const int n0 = blockIdx.x * 128;
    const int m0 = blockIdx.y * 128;
    const int b  = blockIdx.z;
    const int tx = tid & 15;
    const int ty = tid >> 4;

    ull acc[8][4];
#pragma unroll
    for (int i = 0; i < 8; i++)
#pragma unroll
        for (int j = 0; j < 4; j++) acc[i][j] = 0ull;

    for (int k0 = 0; k0 < 512; k0 += 16) {
#pragma unroll
        for (int it = 0; it < 2; it++) {
            int s  = tid + it * 256;
            int kq = s & 3;
            int ml = s >> 2;
            int urow = m0 + ml;
            float4 av = make_float4(0.f, 0.f, 0.f, 0.f);
            if (urow < USTEPS)
                av = *reinterpret_cast<const float4*>(
                    g_catall + ((size_t)urow * 32 + b) * 1024 + k0 + (kq << 2));
            int pc = ml ^ (kq << 2);
            As[(kq << 2) + 0][pc] = av.x;
            As[(kq << 2) + 1][pc] = av.y;
            As[(kq << 2) + 2][pc] = av.z;
            As[(kq << 2) + 3][pc] = av.w;
        }
#pragma unroll
        for (int it = 0; it < 2; it++) {
            int s  = tid + it * 256;
            int dq = s & 3;
            int tl = s >> 2;
            int t  = n0 + tl;
            float4 bv = make_float4(0.f, 0.f, 0.f, 0.f);
            if (t < T1)
                bv = *reinterpret_cast<const float4*>(
                    g_h1 + ((size_t)b * T1 + t) * 512 + k0 + (dq << 2));
            int pc = tl ^ (dq << 2);
            Bs[(dq << 2) + 0][pc] = bv.x;
            Bs[(dq << 2) + 1][pc] = bv.y;
            Bs[(dq << 2) + 2][pc] = bv.z;
            Bs[(dq << 2) + 3][pc] = bv.w;
        }
        __syncthreads();

#pragma unroll
        for (int kk = 0; kk < 16; kk++) {
            const int sw = (kk >> 2) << 2;
            float4 a0 = *reinterpret_cast<const float4*>(&As[kk][(ty << 3) ^ sw]);
            float4 a1 = *reinterpret_cast<const float4*>(&As[kk][((ty << 3) + 4) ^ sw]);
            ulonglong2 bp0 = *reinterpret_cast<const ulonglong2*>(&Bs[kk][(tx << 3) ^ sw]);
            ulonglong2 bp1 = *reinterpret_cast<const ulonglong2*>(&Bs[kk][((tx << 3) + 4) ^ sw]);
            ull b0 = bp0.x, b1 = bp0.y, b2 = bp1.x, b3 = bp1.y;
            float av[8] = {a0.x, a0.y, a0.z, a0.w, a1.x, a1.y, a1.z, a1.w};
#pragma unroll
            for (int i = 0; i < 8; i++) {
                ull a2 = pack2(av[i]);
                fma2(acc[i][0], a2, b0);
                fma2(acc[i][1], a2, b1);
                fma2(acc[i][2], a2, b2);
                fma2(acc[i][3], a2, b3);
            }
        }
        __syncthreads();
    }

    const int t0 = n0 + (tx << 3);
#pragma unroll
    for (int i = 0; i < 8; i++) {
        int urow = m0 + (ty << 3) + i;
        if (urow < USTEPS && t0 < T1) {
            float2 p0v = unpack2(acc[i][0]);
            float2 p1v = unpack2(acc[i][1]);
            float2 p2v = unpack2(acc[i][2]);
            float2 p3v = unpack2(acc[i][3]);
            float* sp = g_scoresall + ((size_t)urow * 32 + b) * T1 + t0;
            *reinterpret_cast<float4*>(sp)     = make_float4(p0v.x, p0v.y, p1v.x, p1v.y);
            *reinterpret_cast<float4*>(sp + 4) = make_float4(p2v.x, p2v.y, p3v.x, p3v.y);
        }
    }
}

// ---------------- Batched softmax over 800 ----------------
__global__ void __launch_bounds__(256) sm800_kernel() {
    const int row = blockIdx.x;
    const int tid = threadIdx.x;
    float* sp = g_scoresall + (size_t)row * T1;
    __shared__ float sa[800];
    __shared__ float red[8], red2[8];
    const int w = tid >> 5, lane = tid & 31;

    float m = -1e30f;
    for (int t = tid; t < 800; t += 256) {
        float v = sp[t];
        sa[t] = v;
        m = fmaxf(m, v);
    }
#pragma unroll
    for (int o = 16; o; o >>= 1) m = fmaxf(m, __shfl_xor_sync(0xffffffffu, m, o));
    if (lane == 0) red[w] = m;
    __syncthreads();
    float mm = red[0];
#pragma unroll
    for (int i = 1; i < 8; i++) mm = fmaxf(mm, red[i]);

    float ps = 0.f;
    for (int t = tid; t < 800; t += 256) {
        float e = expf(sa[t] - mm);
        sa[t] = e;
        ps += e;
    }
#pragma unroll
    for (int o = 16; o; o >>= 1) ps += __shfl_xor_sync(0xffffffffu, ps, o);
    if (lane == 0) red2[w] = ps;
    __syncthreads();
    float sum = 0.f;
#pragma unroll
    for (int i = 0; i < 8; i++) sum += red2[i];
    const float inv = 1.f / sum;

    for (int t = tid; t < 800; t += 256) sp[t] = sa[t] * inv;
}

// ---------------- Batched ctx: per b, alpha[200,800] @ enc_b[800,512] ----------------
__global__ void __launch_bounds__(256, 2) ctx_gemm_kernel() {
    __shared__ __align__(16) float As[16][128];
    __shared__ __align__(16) float Bs[16][128];
    const int tid = threadIdx.x;
    const int n0 = blockIdx.x * 128;
    const int m0 = blockIdx.y * 128;
    const int b  = blockIdx.z;
    const int tx = tid & 15;
    const int ty = tid >> 4;

    ull acc[8][4];
#pragma unroll
    for (int i = 0; i < 8; i++)
#pragma unroll
        for (int j = 0; j < 4; j++) acc[i][j] = 0ull;

    for (int k0 = 0; k0 < 800; k0 += 16) {
#pragma unroll
        for (int it = 0; it < 2; it++) {
            int s  = tid + it * 256;
            int kq = s & 3;
            int ml = s >> 2;
            int u  = m0 + ml;
            float4 av = make_float4(0.f, 0.f, 0.f, 0.f);
            if (u < USTEPS)
                av = *reinterpret_cast<const float4*>(
                    g_scoresall + ((size_t)u * 32 + b) * T1 + k0 + (kq << 2));
            As[(kq << 2) + 0][ml] = av.x;
            As[(kq << 2) + 1][ml] = av.y;
            As[(kq << 2) + 2][ml] = av.z;
            As[(kq << 2) + 3][ml] = av.w;
        }
#pragma unroll
        for (int it = 0; it < 2; it++) {
            int s  = tid + it * 256;
            int cq = s & 31;
            int kr = s >> 5;
            *reinterpret_cast<float4*>(&Bs[kr][cq << 2]) =
                *reinterpret_cast<const float4*>(
                    g_h1 + ((size_t)b * T1 + k0 + kr) * 512 + n0 + (cq << 2));
        }
        __syncthreads();

#pragma unroll
        for (int kk = 0; kk < 16; kk++) {
            float4 a0 = *reinterpret_cast<const float4*>(&As[kk][ty << 3]);
            float4 a1 = *reinterpret_cast<const float4*>(&As[kk][(ty << 3) + 4]);
            ulonglong2 bp0 = *reinterpret_cast<const ulonglong2*>(&Bs[kk][(tx << 3)]);
            ulonglong2 bp1 = *reinterpret_cast<const ulonglong2*>(&Bs[kk][(tx << 3) + 4]);
            ull b0 = bp0.x, b1 = bp0.y, b2 = bp1.x, b3 = bp1.y;
            float av[8] = {a0.x, a0.y, a0.z, a0.w, a1.x, a1.y, a1.z, a1.w};
#pragma unroll
            for (int i = 0; i < 8; i++) {
                ull a2 = pack2(av[i]);
                fma2(acc[i][0], a2, b0);
                fma2(acc[i][1], a2, b1);
                fma2(acc[i][2], a2, b2);
                fma2(acc[i][3], a2, b3);
            }
        }
        __syncthreads();
    }

#pragma unroll
    for (int i = 0; i < 8; i++) {
        int u = m0 + (ty << 3) + i;
        if (u < USTEPS) {
            float2 p0v = unpack2(acc[i][0]);
            float2 p1v = unpack2(acc[i][1]);
            float2 p2v = unpack2(acc[i][2]);
            float2 p3v = unpack2(acc[i][3]);
            float* cp = g_catall + ((size_t)u * 32 + b) * 1024 + 512 + n0 + (tx << 3);
            *reinterpret_cast<float4*>(cp)     = make_float4(p0v.x, p0v.y, p1v.x, p1v.y);
            *reinterpret_cast<float4*>(cp + 4) = make_float4(p2v.x, p2v.y, p3v.x, p3v.y);
        }
    }
}

// ---------------- Batched FC ----------------
__global__ void __launch_bounds__(256, 2) fc_big_kernel(const float* __restrict__ fw,
                                                        const float* __restrict__ fb) {
    __shared__ __align__(16) float As[16][128];
    __shared__ __align__(16) float Bs[16][128];
    const int tid = threadIdx.x;
    const int n0 = blockIdx.x * 128;
    const int m0 = blockIdx.y * 128;
    const int tx = tid & 15;
    const int ty = tid >> 4;

    ull acc[8][4];
#pragma unroll
    for (int i = 0; i < 8; i++)
#pragma unroll
        for (int j = 0; j < 4; j++) acc[i][j] = 0ull;

    for (int p0 = 0; p0 < 1024; p0 += 16) {
#pragma unroll
        for (int it = 0; it < 2; it++) {
            int s  = tid + it * 256;
            int kq = s & 3;
            int ml = s >> 2;
            float4 av = *reinterpret_cast<const float4*>(
                g_catall + ((size_t)(m0 + ml)) * 1024 + p0 + (kq << 2));
            As[(kq << 2) + 0][ml] = av.x;
            As[(kq << 2) + 1][ml] = av.y;
            As[(kq << 2) + 2][ml] = av.z;
            As[(kq << 2) + 3][ml] = av.w;
        }
#pragma unroll
        for (int it = 0; it < 2; it++) {
            int s  = tid + it * 256;
            int cq = s & 31;
            int kr = s >> 5;
            int c  = n0 + (cq << 2);
            float4 v = make_float4(0.f, 0.f, 0.f, 0.f);
            if (c < 1000)
                v = *reinterpret_cast<const float4*>(fw + (size_t)(p0 + kr) * 1000 + c);
            *reinterpret_cast<float4*>(&Bs[kr][cq << 2]) = v;
        }
        __syncthreads();

#pragma unroll
        for (int kk = 0; kk < 16; kk++) {
            float4 a0 = *reinterpret_cast<const float4*>(&As[kk][ty << 3]);
            float4 a1 = *reinterpret_cast<const float4*>(&As[kk][(ty << 3) + 4]);
            ulonglong2 bp0 = *reinterpret_cast<const ulonglong2*>(&Bs[kk][(tx << 3)]);
            ulonglong2 bp1 = *reinterpret_cast<const ulonglong2*>(&Bs[kk][(tx << 3) + 4]);
            ull b0 = bp0.x, b1 = bp0.y, b2 = bp1.x, b3 = bp1.y;
            float av[8] = {a0.x, a0.y, a0.z, a0.w, a1.x, a1.y, a1.z, a1.w};
#pragma unroll
            for (int i = 0; i < 8; i++) {
                ull a2 = pack2(av[i]);
                fma2(acc[i][0], a2, b0);
                fma2(acc[i][1], a2, b1);
                fma2(acc[i][2], a2, b2);
                fma2(acc[i][3], a2, b3);
            }
        }
        __syncthreads();
    }

    const int c0 = n0 + (tx << 3);
    float bias[8];
#pragma unroll
    for (int j = 0; j < 8; j++) bias[j] = (c0 + j < 1000) ? fb[c0 + j] : 0.f;
#pragma unroll
    for (int i = 0; i < 8; i++) {
        int m = m0 + (ty << 3) + i;
        float2 p0v = unpack2(acc[i][0]);
        float2 p1v = unpack2(acc[i][1]);
        float2 p2v = unpack2(acc[i][2]);
        float2 p3v = unpack2(acc[i][3]);
        float4 r0 = make_float4(p0v.x + bias[0], p0v.y + bias[1], p1v.x + bias[2], p1v.y + bias[3]);
        float4 r1 = make_float4(p2v.x + bias[4], p2v.y + bias[5], p3v.x + bias[6], p3v.y + bias[7]);
        float* lp = g_logitsall + (size_t)m * 1000;
        if (c0 < 1000)     *reinterpret_cast<float4*>(lp + c0)     = r0;
        if (c0 + 4 < 1000) *reinterpret_cast<float4*>(lp + c0 + 4) = r1;
    }
}

// ---------------- Batched output softmax ----------------
__global__ void __launch_bounds__(256) outsm_all_kernel(float* __restrict__ out) {
    const int m = blockIdx.x;
    const int u = m >> 5, b = m & 31;
    const int tid = threadIdx.x;
    __shared__ float sh[1000];
    __shared__ float red[8], red2[8];
    const int w = tid >> 5, lane = tid & 31;
    const float* lp = g_logitsall + (size_t)m * 1000;

    float mx = -1e30f;
    for (int c = tid; c < 1000; c += 256) {
        float v = lp[c];
        sh[c] = v;
        mx = fmaxf(mx, v);
    }
#pragma unroll
    for (int o = 16; o; o >>= 1) mx = fmaxf(mx, __shfl_xor_sync(0xffffffffu, mx, o));
    if (lane == 0) red[w] = mx;
    __syncthreads();
    float mm = red[0];
#pragma unroll
    for (int i = 1; i < 8; i++) mm = fmaxf(mm, red[i]);

    float ps = 0.f;
    for (int c = tid; c < 1000; c += 256) {
        float e = expf(sh[c] - mm);
        sh[c] = e;
        ps += e;
    }
#pragma unroll
    for (int o = 16; o; o >>= 1) ps += __shfl_xor_sync(0xffffffffu, ps, o);
    if (lane == 0) red2[w] = ps;
    __syncthreads();
    float sum = 0.f;
#pragma unroll
    for (int i = 0; i < 8; i++) sum += red2[i];
    const float inv = 1.f / sum;

    float* op = out + ((size_t)b * USTEPS + u) * VOCABN;
    for (int c = tid; c < 1000; c += 256) op[c] = sh[c] * inv;
}

// ---------------- launch ----------------
extern "C" void kernel_launch(void* const* d_in, const int* in_sizes, int n_in,
                              void* d_out, int out_size) {
    const float* x        = (const float*)d_in[0];
    const int*   y        = (const int*)  d_in[1];
    const float* bn_gamma = (const float*)d_in[2];
    const float* bn_beta  = (const float*)d_in[3];
    const float* conv0_w  = (const float*)d_in[4];
    const float* conv0_b  = (const float*)d_in[5];
    const float* tcr_w    = (const float*)d_in[6];
    const float* tcr_b    = (const float*)d_in[7];
    const float* gru_k    = (const float*)d_in[8];
    const float* gru_rk   = (const float*)d_in[9];
    const float* gru_b    = (const float*)d_in[10];
    const float* fc_w     = (const float*)d_in[11];
    const float* fc_b     = (const float*)d_in[12];
    float* out = (float*)d_out;

    float *h1, *h2;
    __nv_bfloat16 *shi0, *slo0, *shi1, *slo1, *wth, *wtl;
    cudaGetSymbolAddress((void**)&h1, g_h1);
    cudaGetSymbolAddress((void**)&h2, g_h2);
    cudaGetSymbolAddress((void**)&shi0, g_shi0);
    cudaGetSymbolAddress((void**)&slo0, g_slo0);
    cudaGetSymbolAddress((void**)&shi1, g_shi1);
    cudaGetSymbolAddress((void**)&slo1, g_slo1);
    cudaGetSymbolAddress((void**)&wth, g_wt_hi);
    cudaGetSymbolAddress((void**)&wtl, g_wt_lo);

    // ---- encoder ----
    bn_stats_kernel<<<80, 256>>>(x, bn_gamma, bn_beta);
    zero_h_kernel<<<32, 512>>>();
    dim3 wgrid(80, 16, 4);          // 2560/32, 512/32, 4 layers
    wsplit_kernel<<<wgrid, dim3(32, 8)>>>(tcr_w);

    dim3 cgrid(4, 200);
    conv5x_kernel<80, 1600, 800, 2, 1, true, false, true><<<cgrid, 256>>>(
        x, conv0_w, conv0_b, h1, shi0, slo0);

    const size_t WT = (size_t)512 * 2560;
    dim3 tgrid(4, 200);
    tcr_mma_kernel<true><<<tgrid, 256>>>(
        shi0, slo0, wth + 0 * WT, wtl + 0 * WT, h1, tcr_b + 0 * 512, h2, shi1, slo1);
    tcr_mma_kernel<true><<<tgrid, 256>>>(
        shi1, slo1, wth + 1 * WT, wtl + 1 * WT, h2, tcr_b + 1 * 512, h1, shi0, slo0);
    tcr_mma_kernel<true><<<tgrid, 256>>>(
        shi0, slo0, wth + 2 * WT, wtl + 2 * WT, h1, tcr_b + 2 * 512, h2, shi1, slo1);
    tcr_mma_kernel<false><<<tgrid, 256>>>(
        shi1, slo1, wth + 3 * WT, wtl + 3 * WT, h2, tcr_b + 3 * 512, h1, nullptr, nullptr);
    // enc lives in g_h1 (fp32)

    // ---- pure GRU recurrence: 2 tiny kernels per step ----
    dim3 pgrid(12, 4);
    for (int u = 0; u < USTEPS; u++) {
        gru_part_kernel<<<pgrid, 256>>>(gru_rk, u);
        gru_gates_kernel<<<32, 512>>>(y, gru_k, gru_b, u);
    }

    // ---- batched tail ----
    dim3 sgrid(7, 2, 32);
    scores_gemm_kernel<<<sgrid, 256>>>();
    sm800_kernel<<<USTEPS * B_, 256>>>();
    dim3 xgrid(4, 2, 32);
    ctx_gemm_kernel<<<xgrid, 256>>>();
    dim3 fgrid(8, 50);
    fc_big_kernel<<<fgrid, 256>>>(fc_w, fc_b);
    outsm_all_kernel<<<USTEPS * B_, 256>>>(out);
}